// round 13
// baseline (speedup 1.0000x reference)
#include <cuda_runtime.h>
#include <cuda_fp16.h>
#include <cstdint>

#define S_LEN   2048
#define HID     2048
#define NHEADS  32
#define KVHEADS 8
#define HDIM    64
#define KVW     (KVHEADS * HDIM)   // 512
#define QKVW    (HID + 2 * KVW)    // 3072
#define QKW     (HID + KVW)        // 2560 (Q|K region width)

// ---------------- scratch (__device__ globals; no allocs allowed) ----------
__device__ __align__(16) __half g_HSh[S_LEN * HID];    // hs, half, K-pair interleaved
__device__ __align__(16) __half g_WTh[QKVW * HID];     // WqT|WkT|WvT [N,K] interleaved
__device__ __align__(16) __half g_WoTh[HID * HID];     // WoT [N,K] interleaved
__device__ __align__(16) float  g_QKf[S_LEN * QKW];    // Q|K fp32, plain (pre-rope)
__device__ __align__(16) __half g_QKh[S_LEN * QKW];    // Q|K half, d-pair interleaved
__device__ __align__(16) __half g_Vt[KVW * S_LEN];     // V^T, token-pair p8-interleaved
__device__ __align__(16) __half g_Ah[S_LEN * HID];     // attn out, interleaved

// ---------------- helpers ---------------------------------------------------
__device__ __forceinline__ int p8(int c) { return ((c & 3) << 1) | ((c >> 2) & 1); }
__device__ __forceinline__ int pmap32(int x) {
    return (x & ~15) | (p8((x >> 1) & 7) << 1) | (x & 1);
}
// token index -> permuted position in g_Vt rows (pair p8 within 16-token blocks)
__device__ __forceinline__ int ptok(int t) {
    return (t & ~15) | (p8((t >> 1) & 7) << 1) | (t & 1);
}
__device__ __forceinline__ uint32_t smem_u32(const void* p) {
    uint32_t a;
    asm("{ .reg .u64 t; cvta.to.shared.u64 t, %1; cvt.u32.u64 %0, t; }" : "=r"(a) : "l"(p));
    return a;
}
__device__ __forceinline__ uint32_t pack_h2(float lo, float hi) {
    uint32_t r;
    asm("cvt.rn.f16x2.f32 %0, %1, %2;" : "=r"(r) : "f"(hi), "f"(lo));
    return r;
}
__device__ __forceinline__ float fexp2(float x) {
    float y;
    asm("ex2.approx.f32 %0, %1;" : "=f"(y) : "f"(x));
    return y;
}
__device__ __forceinline__ void mma_f16(float* d, const uint32_t* a,
                                        uint32_t b0, uint32_t b1) {
    asm volatile("mma.sync.aligned.m16n8k16.row.col.f32.f16.f16.f32 "
        "{%0,%1,%2,%3}, {%4,%5,%6,%7}, {%8,%9}, {%0,%1,%2,%3};"
        : "+f"(d[0]), "+f"(d[1]), "+f"(d[2]), "+f"(d[3])
        : "r"(a[0]), "r"(a[1]), "r"(a[2]), "r"(a[3]), "r"(b0), "r"(b1));
}
#define CP_ASYNC16(dst, src) \
    asm volatile("cp.async.cg.shared.global [%0], [%1], 16;" :: "r"(dst), "l"(src) : "memory")
#define CP_COMMIT()  asm volatile("cp.async.commit_group;" ::: "memory")
#define CP_WAIT(n)   asm volatile("cp.async.wait_group %0;" :: "n"(n) : "memory")

#define NSTAGE 3

// ---------------------------------------------------------------------------
// QKV GEMM: 512 threads, CTA tile 128x192, warp 32x48, grid 256 CTAs.
// Output: cols < QKW -> g_QKf fp32; cols >= QKW -> g_Vt (token-interleaved).
// ---------------------------------------------------------------------------
#define QSTAGE_UNITS ((128 + 192) * 32)
#define QGEMM_SMEM_BYTES (NSTAGE * QSTAGE_UNITS * 4)

__device__ __forceinline__ void qkv_issue_stage(uint32_t* sm, int m0, int n0,
                                                int kc, int buf, int tid)
{
    uint32_t* St = sm + buf * QSTAGE_UNITS;
#pragma unroll
    for (int t = 0; t < 5; t++) {
        const int cid = tid + t * 512;       // 0..2559
        const int row = cid >> 3;            // 0..319
        const int j   = cid & 7;
        const uint32_t sw = ((uint32_t)(row & 3)) << 3;
        const uint32_t unit = ((uint32_t)(4 * j)) ^ sw;
        const __half* src = (row < 128)
            ? g_HSh + (size_t)(m0 + row) * HID + kc * 64 + j * 8
            : g_WTh + (size_t)(n0 + row - 128) * HID + kc * 64 + j * 8;
        CP_ASYNC16(smem_u32(St + row * 32) + unit * 4, src);
    }
}

__global__ __launch_bounds__(512) void mma_gemm_qkv()
{
    extern __shared__ uint32_t smu[];
    const int tid  = threadIdx.x;
    const int wid  = tid >> 5;
    const int lane = tid & 31;
    const int g = lane >> 2;
    const int q = lane & 3;
    const int m0 = blockIdx.y * 128;
    const int n0 = blockIdx.x * 192;
    const int wm = (wid & 3) * 32;
    const int wn = (wid >> 2) * 48;
    const int fsw = (g & 3) << 3;

    float acc[2][6][4];
#pragma unroll
    for (int i = 0; i < 2; i++)
#pragma unroll
        for (int j = 0; j < 6; j++)
#pragma unroll
            for (int k = 0; k < 4; k++) acc[i][j][k] = 0.f;

    const int nch = HID / 64;   // 32
    qkv_issue_stage(smu, m0, n0, 0, 0, tid);
    CP_COMMIT();
    qkv_issue_stage(smu, m0, n0, 1, 1, tid);
    CP_COMMIT();

    int buf = 0;
    for (int kc = 0; kc < nch; kc++) {
        if (kc + 1 < nch) { CP_WAIT(1); } else { CP_WAIT(0); }
        __syncthreads();

        const uint32_t* Ab = smu + buf * QSTAGE_UNITS;
        const uint32_t* Bb = Ab + 128 * 32;

#pragma unroll
        for (int ks = 0; ks < 4; ks++) {
            const int scol = ((ks * 8) ^ fsw) + 2 * q;
            uint32_t af[2][4];
#pragma unroll
            for (int fm = 0; fm < 2; fm++) {
                const uint32_t* ar = Ab + (wm + fm * 16 + g) * 32 + scol;
                const uint2 vlo = *(const uint2*)ar;
                const uint2 vhi = *(const uint2*)(ar + 8 * 32);
                af[fm][0] = vlo.x; af[fm][1] = vhi.x;
                af[fm][2] = vlo.y; af[fm][3] = vhi.y;
            }
            uint2 bf[6];
#pragma unroll
            for (int fn = 0; fn < 6; fn++)
                bf[fn] = *(const uint2*)(Bb + (wn + fn * 8 + g) * 32 + scol);
#pragma unroll
            for (int fm = 0; fm < 2; fm++)
#pragma unroll
                for (int fn = 0; fn < 6; fn++)
                    mma_f16(acc[fm][fn], af[fm], bf[fn].x, bf[fn].y);
        }

        if (kc + 2 < nch) {
            const int nb = (buf + 2 >= NSTAGE) ? buf + 2 - NSTAGE : buf + 2;
            qkv_issue_stage(smu, m0, n0, kc + 2, nb, tid);
            CP_COMMIT();
        }
        buf = (buf + 1 == NSTAGE) ? 0 : buf + 1;
    }

#pragma unroll
    for (int fm = 0; fm < 2; fm++) {
        const int r0 = m0 + wm + fm * 16 + g;
#pragma unroll
        for (int fn = 0; fn < 6; fn++) {
            const int c = n0 + wn + fn * 8 + 2 * q;
            if (c >= QKW) {   // V region: transposed, token-interleaved halves
                const int vr = c - QKW;
                const int t0 = ptok(r0);
                const int t1 = ptok(r0 + 8);
                g_Vt[(size_t)vr * S_LEN + t0]       = __float2half_rn(acc[fm][fn][0]);
                g_Vt[(size_t)(vr + 1) * S_LEN + t0] = __float2half_rn(acc[fm][fn][1]);
                g_Vt[(size_t)vr * S_LEN + t1]       = __float2half_rn(acc[fm][fn][2]);
                g_Vt[(size_t)(vr + 1) * S_LEN + t1] = __float2half_rn(acc[fm][fn][3]);
            } else {          // Q|K region: fp32 (rope consumes)
                *(float2*)(g_QKf + (size_t)r0 * QKW + c) =
                    make_float2(acc[fm][fn][0], acc[fm][fn][1]);
                *(float2*)(g_QKf + (size_t)(r0 + 8) * QKW + c) =
                    make_float2(acc[fm][fn][2], acc[fm][fn][3]);
            }
        }
    }
}

// ---------------------------------------------------------------------------
// Wo GEMM: proven 256-thread 128x128 kernel.
// ---------------------------------------------------------------------------
#define STAGE_UNITS (2 * 128 * 32)
#define GEMM_SMEM_BYTES (NSTAGE * STAGE_UNITS * 4)

__device__ __forceinline__ void gemm_issue_stage(const __half* A, const __half* Bt,
                                                 uint32_t* sm, int m0, int n0, int Kh,
                                                 int kc, int buf, int lrow, int lsel)
{
    uint32_t* Ad = sm + buf * STAGE_UNITS;
    uint32_t* Bd = Ad + 128 * 32;
    const __half* Ap = A  + (size_t)(m0 + lrow) * Kh + kc * 64 + lsel * 32;
    const __half* Bp = Bt + (size_t)(n0 + lrow) * Kh + kc * 64 + lsel * 32;
    const uint32_t sw = (lrow & 3) << 3;
    uint32_t da = smem_u32(Ad + lrow * 32);
    uint32_t db = smem_u32(Bd + lrow * 32);
#pragma unroll
    for (int j = 0; j < 4; j++) {
        const uint32_t u = ((uint32_t)(lsel * 16 + 4 * j) ^ sw) * 4;
        CP_ASYNC16(da + u, Ap + j * 8);
        CP_ASYNC16(db + u, Bp + j * 8);
    }
}

__global__ __launch_bounds__(256) void mma_gemm(const __half* __restrict__ A,
                                                const __half* __restrict__ Bt,
                                                float* __restrict__ Cf,
                                                int M, int N, int Kh)
{
    extern __shared__ uint32_t smu[];
    const int tid  = threadIdx.x;
    const int wid  = tid >> 5;
    const int lane = tid & 31;
    const int g = lane >> 2;
    const int q = lane & 3;
    const int m0 = blockIdx.y * 128;
    const int n0 = blockIdx.x * 128;
    const int wm = (wid & 1) * 64;
    const int wn = (wid >> 1) * 32;

    const int lrow = tid >> 1;
    const int lsel = tid & 1;
    const int fsw  = (g & 3) << 3;

    float acc[4][4][4];
#pragma unroll
    for (int i = 0; i < 4; i++)
#pragma unroll
        for (int j = 0; j < 4; j++)
#pragma unroll
            for (int k = 0; k < 4; k++) acc[i][j][k] = 0.f;

    const int nch = Kh / 64;
    gemm_issue_stage(A, Bt, smu, m0, n0, Kh, 0, 0, lrow, lsel);
    CP_COMMIT();
    if (nch > 1) {
        gemm_issue_stage(A, Bt, smu, m0, n0, Kh, 1, 1, lrow, lsel);
        CP_COMMIT();
    }

    int buf = 0;
    for (int kc = 0; kc < nch; kc++) {
        if (kc + 1 < nch) { CP_WAIT(1); } else { CP_WAIT(0); }
        __syncthreads();

        const uint32_t* Ab = smu + buf * STAGE_UNITS;
        const uint32_t* Bb = Ab + 128 * 32;

#pragma unroll
        for (int ks = 0; ks < 4; ks++) {
            const int scol = ((ks * 8) ^ fsw) + 2 * q;
            uint32_t af[4][4];
#pragma unroll
            for (int fm = 0; fm < 4; fm++) {
                const uint32_t* ar = Ab + (wm + fm * 16 + g) * 32 + scol;
                const uint2 vlo = *(const uint2*)ar;
                const uint2 vhi = *(const uint2*)(ar + 8 * 32);
                af[fm][0] = vlo.x; af[fm][1] = vhi.x;
                af[fm][2] = vlo.y; af[fm][3] = vhi.y;
            }
            uint2 bf[4];
#pragma unroll
            for (int fn = 0; fn < 4; fn++)
                bf[fn] = *(const uint2*)(Bb + (wn + fn * 8 + g) * 32 + scol);
#pragma unroll
            for (int fm = 0; fm < 4; fm++)
#pragma unroll
                for (int fn = 0; fn < 4; fn++)
                    mma_f16(acc[fm][fn], af[fm], bf[fn].x, bf[fn].y);
        }

        if (kc + 2 < nch) {
            const int nb = (buf + 2 >= NSTAGE) ? buf + 2 - NSTAGE : buf + 2;
            gemm_issue_stage(A, Bt, smu, m0, n0, Kh, kc + 2, nb, lrow, lsel);
            CP_COMMIT();
        }
        buf = (buf + 1 == NSTAGE) ? 0 : buf + 1;
    }

#pragma unroll
    for (int fm = 0; fm < 4; fm++) {
        const int r0 = m0 + wm + fm * 16 + g;
#pragma unroll
        for (int fn = 0; fn < 4; fn++) {
            const int c = n0 + wn + fn * 8 + 2 * q;
            *(float2*)(Cf + (size_t)r0 * N + c) =
                make_float2(acc[fm][fn][0], acc[fm][fn][1]);
            *(float2*)(Cf + (size_t)(r0 + 8) * N + c) =
                make_float2(acc[fm][fn][2], acc[fm][fn][3]);
        }
    }
}

// ---------------------------------------------------------------------------
// Fused prep: weight transposes (half, K-dim pmap) + hs -> half (cols pmap).
// ---------------------------------------------------------------------------
__global__ void prep_all(const float* __restrict__ hs,
                         const float* __restrict__ Wq, const float* __restrict__ Wk,
                         const float* __restrict__ Wv, const float* __restrict__ Wo)
{
    __shared__ float t[32][33];
    const int z = blockIdx.z;
    const int x = threadIdx.x, y = threadIdx.y;
    const int bx = blockIdx.x * 32;
    const int by = blockIdx.y * 32;
    const int px = pmap32(x);

    if (z == 4) {
        const float* src = hs + (size_t)by * HID + bx;
        __half* dst = g_HSh + (size_t)by * HID + bx;
#pragma unroll
        for (int i = 0; i < 32; i += 8)
            dst[(size_t)(y + i) * HID + px] = __float2half_rn(src[(size_t)(y + i) * HID + x]);
        return;
    }

    const float* src;
    __half* dst;
    int C;
    if (z == 0)      { src = Wq; dst = g_WTh;                              C = HID; }
    else if (z == 1) { src = Wo; dst = g_WoTh;                             C = HID; }
    else if (z == 2) { src = Wk; dst = g_WTh + (size_t)HID * HID;          C = KVW; }
    else             { src = Wv; dst = g_WTh + (size_t)(HID + KVW) * HID;  C = KVW; }
    if (bx >= C) return;

#pragma unroll
    for (int i = 0; i < 32; i += 8)
        t[y + i][x] = src[(size_t)(by + y + i) * C + bx + x];
    __syncthreads();
#pragma unroll
    for (int i = 0; i < 32; i += 8)
        dst[(size_t)(bx + y + i) * HID + by + px] = __float2half_rn(t[x][y + i]);
}

// ---------------------------------------------------------------------------
// RoPE: g_QKf (fp32) -> g_QKh (half, d-pair interleaved).
// Q scale = log2(e)/8 so attention softmax uses raw ex2.
// ---------------------------------------------------------------------------
__global__ __launch_bounds__(256) void rope_kernel()
{
    const int s = blockIdx.x;
    const int w = threadIdx.x >> 5;
    const int i = threadIdx.x & 31;
    const int h = blockIdx.y * 8 + w;      // 0..39

    const bool isQ = (h < NHEADS);
    const int base = isQ ? h * HDIM : HID + (h - NHEADS) * HDIM;
    const float scale = isQ ? 0.125f * 1.4426950408889634f : 1.0f;

    const float* src = g_QKf + (size_t)s * QKW + base;
    __half* dst = g_QKh + (size_t)s * QKW + base;

    float x1 = src[i];
    float x2 = src[i + 32];
    const float LN10000 = 9.210340371976184f;
    float inv = expf(-(float)i * (LN10000 / 32.0f));
    float ang = (float)s * inv;
    float c, sn;
    sincosf(ang, &sn, &c);
    dst[pmap32(i)]      = __float2half_rn((x1 * c - x2 * sn) * scale);
    dst[pmap32(i + 32)] = __float2half_rn((x2 * c + x1 * sn) * scale);
}

// ---------------------------------------------------------------------------
// fp16 tensor-core causal GQA flash attention, LOAD-BALANCED:
// each CTA processes the qb pair (15 - by, by): T = 34 tiles for EVERY CTA;
// grid (32, 8) = 256 CTAs = one full wave at 2 CTAs/SM.
// V in g_Vt is token-pair interleaved -> PV B-loads are conflict-free LDS.64
// with the same (row&3)<<3 swizzle as K.
// ---------------------------------------------------------------------------
#define ATT_Q_UNITS  (128 * 32)
#define ATT_KV_UNITS (64 * 32)
#define ATT_SMEM_BYTES ((ATT_Q_UNITS + 4 * ATT_KV_UNITS) * 4)

__device__ __forceinline__ void attn_issue_kv(uint32_t* Kd, uint32_t* Vd,
                                              int k0, int kvh, int tid)
{
    const int lr = tid >> 2;
    const int jb = (tid & 3) * 2;
    const __half* kg = g_QKh + (size_t)(k0 + lr) * QKW + HID + kvh * HDIM;
    const __half* vg = g_Vt + (size_t)(kvh * HDIM + lr) * S_LEN + k0;
    uint32_t kd = smem_u32(Kd + lr * 32);
    uint32_t vd = smem_u32(Vd + lr * 32);
    const uint32_t sw = (lr & 3) << 3;
#pragma unroll
    for (int e = 0; e < 2; e++) {
        const int j = jb + e;
        const uint32_t u = (((uint32_t)(4 * j)) ^ sw) * 4;
        CP_ASYNC16(kd + u, kg + j * 8);
        CP_ASYNC16(vd + u, vg + j * 8);
    }
}

__global__ __launch_bounds__(256, 2) void attn_mma()
{
    extern __shared__ uint32_t smu[];
    uint32_t* Qs  = smu;
    uint32_t* Kb0 = smu + ATT_Q_UNITS;
    uint32_t* Kb1 = Kb0 + ATT_KV_UNITS;
    uint32_t* Vb0 = Kb1 + ATT_KV_UNITS;
    uint32_t* Vb1 = Vb0 + ATT_KV_UNITS;

    const int head = blockIdx.x;
    const int kvh  = head % KVHEADS;
    const int tid  = threadIdx.x;
    const int wid  = tid >> 5;
    const int lane = tid & 31;
    const int g = lane >> 2, q = lane & 3;
    const int wm = wid * 16;
    const int fsw = (g & 3) << 3;

#pragma unroll 1
    for (int seg = 0; seg < 2; seg++) {
        const int qb = seg ? (int)blockIdx.y : 15 - (int)blockIdx.y;
        const int q0 = qb * 128;
        const int T  = 2 * qb + 2;

        attn_issue_kv(Kb0, Vb0, 0, kvh, tid);
        CP_COMMIT();

        // Q tile (128 x 64 halves) -> Qs (interleaved by rope; swizzled here)
        {
            const int r  = tid >> 1;
            const int s0 = (tid & 1) * 4;
            const int sw = (r & 3) << 3;
            const __half* src = g_QKh + (size_t)(q0 + r) * QKW + head * HDIM
                              + (tid & 1) * 32;
            uint32_t* dst = Qs + r * 32;
#pragma unroll
            for (int j = 0; j < 4; j++) {
                const uint4 v = *(const uint4*)(src + j * 8);
                *(uint4*)(dst + (((s0 + j) * 4) ^ sw)) = v;
            }
        }
        __syncthreads();

        uint32_t qf[4][4];
#pragma unroll
        for (int ks = 0; ks < 4; ks++) {
            const int scol = ((ks * 8) ^ fsw) + 2 * q;
            const uint32_t* a = Qs + (wm + g) * 32 + scol;
            const uint2 vlo = *(const uint2*)a;
            const uint2 vhi = *(const uint2*)(a + 8 * 32);
            qf[ks][0] = vlo.x; qf[ks][1] = vhi.x;
            qf[ks][2] = vlo.y; qf[ks][3] = vhi.y;
        }

        float o[8][4];
#pragma unroll
        for (int nf = 0; nf < 8; nf++)
#pragma unroll
            for (int j = 0; j < 4; j++) o[nf][j] = 0.f;
        float l0 = 0.f, l1 = 0.f;

        for (int t = 0; t < T; t++) {
            if (t + 1 < T) {
                attn_issue_kv(((t + 1) & 1) ? Kb1 : Kb0, ((t + 1) & 1) ? Vb1 : Vb0,
                              (t + 1) * 64, kvh, tid);
                CP_COMMIT();
                CP_WAIT(1);
            } else {
                CP_WAIT(0);
            }
            __syncthreads();

            const int k0 = t * 64;
            const bool active = (k0 <= q0 + wm + 15);   // warp-uniform

            if (active) {
                const uint32_t* Ks = (t & 1) ? Kb1 : Kb0;
                const uint32_t* Vs = (t & 1) ? Vb1 : Vb0;

                // ---- S = Q K^T (base-2 log domain) ----
                float s[8][4];
#pragma unroll
                for (int nf = 0; nf < 8; nf++)
#pragma unroll
                    for (int j = 0; j < 4; j++) s[nf][j] = 0.f;

#pragma unroll
                for (int ks = 0; ks < 4; ks++) {
                    const int scol = ((ks * 8) ^ fsw) + 2 * q;
#pragma unroll
                    for (int nf = 0; nf < 8; nf++) {
                        const uint2 vb = *(const uint2*)(Ks + (nf * 8 + g) * 32 + scol);
                        mma_f16(s[nf], qf[ks], vb.x, vb.y);
                    }
                }

                // ---- causal mask ----
                if (k0 + 63 > q0 + wm) {
                    const int row0 = q0 + wm + g;
#pragma unroll
                    for (int nf = 0; nf < 8; nf++) {
                        const int c = k0 + nf * 8 + 2 * q;
                        if (c     > row0)     s[nf][0] = -1e30f;
                        if (c + 1 > row0)     s[nf][1] = -1e30f;
                        if (c     > row0 + 8) s[nf][2] = -1e30f;
                        if (c + 1 > row0 + 8) s[nf][3] = -1e30f;
                    }
                }

                // ---- softmax numerator: raw ex2 ----
                float rs0 = 0.f, rs1 = 0.f;
#pragma unroll
                for (int nf = 0; nf < 8; nf++) {
                    s[nf][0] = fexp2(s[nf][0]);
                    s[nf][1] = fexp2(s[nf][1]);
                    s[nf][2] = fexp2(s[nf][2]);
                    s[nf][3] = fexp2(s[nf][3]);
                    rs0 += s[nf][0] + s[nf][1];
                    rs1 += s[nf][2] + s[nf][3];
                }
                rs0 += __shfl_xor_sync(0xffffffffu, rs0, 1);
                rs0 += __shfl_xor_sync(0xffffffffu, rs0, 2);
                rs1 += __shfl_xor_sync(0xffffffffu, rs1, 1);
                rs1 += __shfl_xor_sync(0xffffffffu, rs1, 2);
                l0 += rs0;
                l1 += rs1;

                // ---- O += P V : token-interleaved V -> LDS.64 B frags ----
#pragma unroll
                for (int kb = 0; kb < 4; kb++) {
                    uint32_t pa[4];
                    pa[0] = pack_h2(s[2 * kb][0],     s[2 * kb][1]);
                    pa[1] = pack_h2(s[2 * kb][2],     s[2 * kb][3]);
                    pa[2] = pack_h2(s[2 * kb + 1][0], s[2 * kb + 1][1]);
                    pa[3] = pack_h2(s[2 * kb + 1][2], s[2 * kb + 1][3]);
                    const int vcol = ((8 * kb) ^ fsw) + 2 * q;
#pragma unroll
                    for (int nf = 0; nf < 8; nf++) {
                        const uint2 vb = *(const uint2*)(Vs + (nf * 8 + g) * 32 + vcol);
                        mma_f16(o[nf], pa, vb.x, vb.y);
                    }
                }
            }
            __syncthreads();
        }

        // ---- epilogue: normalize, write g_Ah interleaved ----
        const float inv0 = 1.f / l0;
        const float inv1 = 1.f / l1;
        const int row0 = q0 + wm + g;
        half2* Ah2 = (half2*)g_Ah;
#pragma unroll
        for (int nf = 0; nf < 8; nf++) {
            const int jj = 4 * nf + q;
            const int pos = head * 32 + ((jj & ~7) | p8(jj & 7));
            Ah2[(size_t)row0 * (HID / 2) + pos] =
                __floats2half2_rn(o[nf][0] * inv0, o[nf][1] * inv0);
            Ah2[(size_t)(row0 + 8) * (HID / 2) + pos] =
                __floats2half2_rn(o[nf][2] * inv1, o[nf][3] * inv1);
        }
        __syncthreads();   // smem safe for next segment
    }
}

// ---------------------------------------------------------------------------
extern "C" void kernel_launch(void* const* d_in, const int* in_sizes, int n_in,
                              void* d_out, int out_size)
{
    const float* hs = (const float*)d_in[0];
    const float* Wq = (const float*)d_in[1];
    const float* Wk = (const float*)d_in[2];
    const float* Wv = (const float*)d_in[3];
    const float* Wo = (const float*)d_in[4];
    float* out = (float*)d_out;

    __half *Ah, *WoTh;
    cudaGetSymbolAddress((void**)&Ah, g_Ah);
    cudaGetSymbolAddress((void**)&WoTh, g_WoTh);

    cudaFuncSetAttribute(mma_gemm_qkv, cudaFuncAttributeMaxDynamicSharedMemorySize,
                         QGEMM_SMEM_BYTES);
    cudaFuncSetAttribute(mma_gemm, cudaFuncAttributeMaxDynamicSharedMemorySize,
                         GEMM_SMEM_BYTES);
    cudaFuncSetAttribute(attn_mma, cudaFuncAttributeMaxDynamicSharedMemorySize,
                         ATT_SMEM_BYTES);

    // Prep: weights -> half transposed interleaved; hs -> half interleaved
    prep_all<<<dim3(64, 64, 5), dim3(32, 8)>>>(hs, Wq, Wk, Wv, Wo);

    // Fused QKV projection: Q|K -> fp32, V -> Vt half (token-interleaved)
    mma_gemm_qkv<<<dim3(QKVW / 192, S_LEN / 128), 512, QGEMM_SMEM_BYTES>>>();

    // RoPE: fp32 -> half interleaved (Q pre-scaled by log2e/8)
    rope_kernel<<<dim3(S_LEN, 5), 256>>>();

    // fp16 tensor-core causal attention, load-balanced qb pairs
    attn_mma<<<dim3(NHEADS, 8), 256, ATT_SMEM_BYTES>>>();

    // Output projection (fp32 out)
    mma_gemm<<<dim3(HID / 128, S_LEN / 128), 256, GEMM_SMEM_BYTES>>>(
        Ah, WoTh, out, S_LEN, HID, HID);
}

// round 14
// speedup vs baseline: 1.0520x; 1.0520x over previous
#include <cuda_runtime.h>
#include <cuda_fp16.h>
#include <cstdint>

#define S_LEN   2048
#define HID     2048
#define NHEADS  32
#define KVHEADS 8
#define HDIM    64
#define KVW     (KVHEADS * HDIM)   // 512
#define QKVW    (HID + 2 * KVW)    // 3072
#define QKW     (HID + KVW)        // 2560 (Q|K region width)

// ---------------- scratch (__device__ globals; no allocs allowed) ----------
__device__ __align__(16) __half g_HSh[S_LEN * HID];    // hs, half, K-pair interleaved
__device__ __align__(16) __half g_WTh[QKVW * HID];     // WqT|WkT|WvT [N,K] interleaved
__device__ __align__(16) __half g_WoTh[HID * HID];     // WoT [N,K] interleaved
__device__ __align__(16) float  g_QKf[S_LEN * QKW];    // Q|K fp32, plain (pre-rope)
__device__ __align__(16) __half g_QKh[S_LEN * QKW];    // Q|K half, d-pair interleaved
__device__ __align__(16) __half g_Vt[KVW * S_LEN];     // V^T, token-pair p8-interleaved
__device__ __align__(16) __half g_Ah[S_LEN * HID];     // attn out, interleaved

// ---------------- helpers ---------------------------------------------------
__device__ __forceinline__ int p8(int c) { return ((c & 3) << 1) | ((c >> 2) & 1); }
__device__ __forceinline__ int pmap32(int x) {
    return (x & ~15) | (p8((x >> 1) & 7) << 1) | (x & 1);
}
// token index -> permuted position in g_Vt rows (pair p8 within 16-token blocks)
__device__ __forceinline__ int ptok(int t) {
    return (t & ~15) | (p8((t >> 1) & 7) << 1) | (t & 1);
}
__device__ __forceinline__ uint32_t smem_u32(const void* p) {
    uint32_t a;
    asm("{ .reg .u64 t; cvta.to.shared.u64 t, %1; cvt.u32.u64 %0, t; }" : "=r"(a) : "l"(p));
    return a;
}
__device__ __forceinline__ uint32_t pack_h2(float lo, float hi) {
    uint32_t r;
    asm("cvt.rn.f16x2.f32 %0, %1, %2;" : "=r"(r) : "f"(hi), "f"(lo));
    return r;
}
__device__ __forceinline__ float fexp2(float x) {
    float y;
    asm("ex2.approx.f32 %0, %1;" : "=f"(y) : "f"(x));
    return y;
}
__device__ __forceinline__ void mma_f16(float* d, const uint32_t* a,
                                        uint32_t b0, uint32_t b1) {
    asm volatile("mma.sync.aligned.m16n8k16.row.col.f32.f16.f16.f32 "
        "{%0,%1,%2,%3}, {%4,%5,%6,%7}, {%8,%9}, {%0,%1,%2,%3};"
        : "+f"(d[0]), "+f"(d[1]), "+f"(d[2]), "+f"(d[3])
        : "r"(a[0]), "r"(a[1]), "r"(a[2]), "r"(a[3]), "r"(b0), "r"(b1));
}
#define CP_ASYNC16(dst, src) \
    asm volatile("cp.async.cg.shared.global [%0], [%1], 16;" :: "r"(dst), "l"(src) : "memory")
#define CP_COMMIT()  asm volatile("cp.async.commit_group;" ::: "memory")
#define CP_WAIT(n)   asm volatile("cp.async.wait_group %0;" :: "n"(n) : "memory")

#define NSTAGE 3

// ---------------------------------------------------------------------------
// QKV GEMM: 512 threads, CTA tile 128x192, warp 32x48, grid 256 CTAs.
// Output: cols < QKW -> g_QKf fp32; cols >= QKW -> g_Vt (token-interleaved).
// ---------------------------------------------------------------------------
#define QSTAGE_UNITS ((128 + 192) * 32)
#define QGEMM_SMEM_BYTES (NSTAGE * QSTAGE_UNITS * 4)

__device__ __forceinline__ void qkv_issue_stage(uint32_t* sm, int m0, int n0,
                                                int kc, int buf, int tid)
{
    uint32_t* St = sm + buf * QSTAGE_UNITS;
#pragma unroll
    for (int t = 0; t < 5; t++) {
        const int cid = tid + t * 512;       // 0..2559
        const int row = cid >> 3;            // 0..319
        const int j   = cid & 7;
        const uint32_t sw = ((uint32_t)(row & 3)) << 3;
        const uint32_t unit = ((uint32_t)(4 * j)) ^ sw;
        const __half* src = (row < 128)
            ? g_HSh + (size_t)(m0 + row) * HID + kc * 64 + j * 8
            : g_WTh + (size_t)(n0 + row - 128) * HID + kc * 64 + j * 8;
        CP_ASYNC16(smem_u32(St + row * 32) + unit * 4, src);
    }
}

__global__ __launch_bounds__(512) void mma_gemm_qkv()
{
    extern __shared__ uint32_t smu[];
    const int tid  = threadIdx.x;
    const int wid  = tid >> 5;
    const int lane = tid & 31;
    const int g = lane >> 2;
    const int q = lane & 3;
    const int m0 = blockIdx.y * 128;
    const int n0 = blockIdx.x * 192;
    const int wm = (wid & 3) * 32;
    const int wn = (wid >> 2) * 48;
    const int fsw = (g & 3) << 3;

    float acc[2][6][4];
#pragma unroll
    for (int i = 0; i < 2; i++)
#pragma unroll
        for (int j = 0; j < 6; j++)
#pragma unroll
            for (int k = 0; k < 4; k++) acc[i][j][k] = 0.f;

    const int nch = HID / 64;   // 32
    qkv_issue_stage(smu, m0, n0, 0, 0, tid);
    CP_COMMIT();
    qkv_issue_stage(smu, m0, n0, 1, 1, tid);
    CP_COMMIT();

    int buf = 0;
    for (int kc = 0; kc < nch; kc++) {
        if (kc + 1 < nch) { CP_WAIT(1); } else { CP_WAIT(0); }
        __syncthreads();

        const uint32_t* Ab = smu + buf * QSTAGE_UNITS;
        const uint32_t* Bb = Ab + 128 * 32;

#pragma unroll
        for (int ks = 0; ks < 4; ks++) {
            const int scol = ((ks * 8) ^ fsw) + 2 * q;
            uint32_t af[2][4];
#pragma unroll
            for (int fm = 0; fm < 2; fm++) {
                const uint32_t* ar = Ab + (wm + fm * 16 + g) * 32 + scol;
                const uint2 vlo = *(const uint2*)ar;
                const uint2 vhi = *(const uint2*)(ar + 8 * 32);
                af[fm][0] = vlo.x; af[fm][1] = vhi.x;
                af[fm][2] = vlo.y; af[fm][3] = vhi.y;
            }
            uint2 bf[6];
#pragma unroll
            for (int fn = 0; fn < 6; fn++)
                bf[fn] = *(const uint2*)(Bb + (wn + fn * 8 + g) * 32 + scol);
#pragma unroll
            for (int fm = 0; fm < 2; fm++)
#pragma unroll
                for (int fn = 0; fn < 6; fn++)
                    mma_f16(acc[fm][fn], af[fm], bf[fn].x, bf[fn].y);
        }

        if (kc + 2 < nch) {
            const int nb = (buf + 2 >= NSTAGE) ? buf + 2 - NSTAGE : buf + 2;
            qkv_issue_stage(smu, m0, n0, kc + 2, nb, tid);
            CP_COMMIT();
        }
        buf = (buf + 1 == NSTAGE) ? 0 : buf + 1;
    }

#pragma unroll
    for (int fm = 0; fm < 2; fm++) {
        const int r0 = m0 + wm + fm * 16 + g;
#pragma unroll
        for (int fn = 0; fn < 6; fn++) {
            const int c = n0 + wn + fn * 8 + 2 * q;
            if (c >= QKW) {   // V region: transposed, token-interleaved halves
                const int vr = c - QKW;
                const int t0 = ptok(r0);
                const int t1 = ptok(r0 + 8);
                g_Vt[(size_t)vr * S_LEN + t0]       = __float2half_rn(acc[fm][fn][0]);
                g_Vt[(size_t)(vr + 1) * S_LEN + t0] = __float2half_rn(acc[fm][fn][1]);
                g_Vt[(size_t)vr * S_LEN + t1]       = __float2half_rn(acc[fm][fn][2]);
                g_Vt[(size_t)(vr + 1) * S_LEN + t1] = __float2half_rn(acc[fm][fn][3]);
            } else {          // Q|K region: fp32 (rope consumes)
                *(float2*)(g_QKf + (size_t)r0 * QKW + c) =
                    make_float2(acc[fm][fn][0], acc[fm][fn][1]);
                *(float2*)(g_QKf + (size_t)(r0 + 8) * QKW + c) =
                    make_float2(acc[fm][fn][2], acc[fm][fn][3]);
            }
        }
    }
}

// ---------------------------------------------------------------------------
// Wo GEMM: proven 256-thread 128x128 kernel.
// ---------------------------------------------------------------------------
#define STAGE_UNITS (2 * 128 * 32)
#define GEMM_SMEM_BYTES (NSTAGE * STAGE_UNITS * 4)

__device__ __forceinline__ void gemm_issue_stage(const __half* A, const __half* Bt,
                                                 uint32_t* sm, int m0, int n0, int Kh,
                                                 int kc, int buf, int lrow, int lsel)
{
    uint32_t* Ad = sm + buf * STAGE_UNITS;
    uint32_t* Bd = Ad + 128 * 32;
    const __half* Ap = A  + (size_t)(m0 + lrow) * Kh + kc * 64 + lsel * 32;
    const __half* Bp = Bt + (size_t)(n0 + lrow) * Kh + kc * 64 + lsel * 32;
    const uint32_t sw = (lrow & 3) << 3;
    uint32_t da = smem_u32(Ad + lrow * 32);
    uint32_t db = smem_u32(Bd + lrow * 32);
#pragma unroll
    for (int j = 0; j < 4; j++) {
        const uint32_t u = ((uint32_t)(lsel * 16 + 4 * j) ^ sw) * 4;
        CP_ASYNC16(da + u, Ap + j * 8);
        CP_ASYNC16(db + u, Bp + j * 8);
    }
}

__global__ __launch_bounds__(256) void mma_gemm(const __half* __restrict__ A,
                                                const __half* __restrict__ Bt,
                                                float* __restrict__ Cf,
                                                int M, int N, int Kh)
{
    extern __shared__ uint32_t smu[];
    const int tid  = threadIdx.x;
    const int wid  = tid >> 5;
    const int lane = tid & 31;
    const int g = lane >> 2;
    const int q = lane & 3;
    const int m0 = blockIdx.y * 128;
    const int n0 = blockIdx.x * 128;
    const int wm = (wid & 1) * 64;
    const int wn = (wid >> 1) * 32;

    const int lrow = tid >> 1;
    const int lsel = tid & 1;
    const int fsw  = (g & 3) << 3;

    float acc[4][4][4];
#pragma unroll
    for (int i = 0; i < 4; i++)
#pragma unroll
        for (int j = 0; j < 4; j++)
#pragma unroll
            for (int k = 0; k < 4; k++) acc[i][j][k] = 0.f;

    const int nch = Kh / 64;
    gemm_issue_stage(A, Bt, smu, m0, n0, Kh, 0, 0, lrow, lsel);
    CP_COMMIT();
    if (nch > 1) {
        gemm_issue_stage(A, Bt, smu, m0, n0, Kh, 1, 1, lrow, lsel);
        CP_COMMIT();
    }

    int buf = 0;
    for (int kc = 0; kc < nch; kc++) {
        if (kc + 1 < nch) { CP_WAIT(1); } else { CP_WAIT(0); }
        __syncthreads();

        const uint32_t* Ab = smu + buf * STAGE_UNITS;
        const uint32_t* Bb = Ab + 128 * 32;

#pragma unroll
        for (int ks = 0; ks < 4; ks++) {
            const int scol = ((ks * 8) ^ fsw) + 2 * q;
            uint32_t af[4][4];
#pragma unroll
            for (int fm = 0; fm < 4; fm++) {
                const uint32_t* ar = Ab + (wm + fm * 16 + g) * 32 + scol;
                const uint2 vlo = *(const uint2*)ar;
                const uint2 vhi = *(const uint2*)(ar + 8 * 32);
                af[fm][0] = vlo.x; af[fm][1] = vhi.x;
                af[fm][2] = vlo.y; af[fm][3] = vhi.y;
            }
            uint2 bf[4];
#pragma unroll
            for (int fn = 0; fn < 4; fn++)
                bf[fn] = *(const uint2*)(Bb + (wn + fn * 8 + g) * 32 + scol);
#pragma unroll
            for (int fm = 0; fm < 4; fm++)
#pragma unroll
                for (int fn = 0; fn < 4; fn++)
                    mma_f16(acc[fm][fn], af[fm], bf[fn].x, bf[fn].y);
        }

        if (kc + 2 < nch) {
            const int nb = (buf + 2 >= NSTAGE) ? buf + 2 - NSTAGE : buf + 2;
            gemm_issue_stage(A, Bt, smu, m0, n0, Kh, kc + 2, nb, lrow, lsel);
            CP_COMMIT();
        }
        buf = (buf + 1 == NSTAGE) ? 0 : buf + 1;
    }

#pragma unroll
    for (int fm = 0; fm < 4; fm++) {
        const int r0 = m0 + wm + fm * 16 + g;
#pragma unroll
        for (int fn = 0; fn < 4; fn++) {
            const int c = n0 + wn + fn * 8 + 2 * q;
            *(float2*)(Cf + (size_t)r0 * N + c) =
                make_float2(acc[fm][fn][0], acc[fm][fn][1]);
            *(float2*)(Cf + (size_t)(r0 + 8) * N + c) =
                make_float2(acc[fm][fn][2], acc[fm][fn][3]);
        }
    }
}

// ---------------------------------------------------------------------------
// Fused prep: weight transposes (half, K-dim pmap) + hs -> half (cols pmap).
// ---------------------------------------------------------------------------
__global__ void prep_all(const float* __restrict__ hs,
                         const float* __restrict__ Wq, const float* __restrict__ Wk,
                         const float* __restrict__ Wv, const float* __restrict__ Wo)
{
    __shared__ float t[32][33];
    const int z = blockIdx.z;
    const int x = threadIdx.x, y = threadIdx.y;
    const int bx = blockIdx.x * 32;
    const int by = blockIdx.y * 32;
    const int px = pmap32(x);

    if (z == 4) {
        const float* src = hs + (size_t)by * HID + bx;
        __half* dst = g_HSh + (size_t)by * HID + bx;
#pragma unroll
        for (int i = 0; i < 32; i += 8)
            dst[(size_t)(y + i) * HID + px] = __float2half_rn(src[(size_t)(y + i) * HID + x]);
        return;
    }

    const float* src;
    __half* dst;
    int C;
    if (z == 0)      { src = Wq; dst = g_WTh;                              C = HID; }
    else if (z == 1) { src = Wo; dst = g_WoTh;                             C = HID; }
    else if (z == 2) { src = Wk; dst = g_WTh + (size_t)HID * HID;          C = KVW; }
    else             { src = Wv; dst = g_WTh + (size_t)(HID + KVW) * HID;  C = KVW; }
    if (bx >= C) return;

#pragma unroll
    for (int i = 0; i < 32; i += 8)
        t[y + i][x] = src[(size_t)(by + y + i) * C + bx + x];
    __syncthreads();
#pragma unroll
    for (int i = 0; i < 32; i += 8)
        dst[(size_t)(bx + y + i) * HID + by + px] = __float2half_rn(t[x][y + i]);
}

// ---------------------------------------------------------------------------
// RoPE: g_QKf (fp32) -> g_QKh (half, d-pair interleaved).
// Q scale = log2(e)/8 so attention softmax uses raw ex2.
// ---------------------------------------------------------------------------
__global__ __launch_bounds__(256) void rope_kernel()
{
    const int s = blockIdx.x;
    const int w = threadIdx.x >> 5;
    const int i = threadIdx.x & 31;
    const int h = blockIdx.y * 8 + w;      // 0..39

    const bool isQ = (h < NHEADS);
    const int base = isQ ? h * HDIM : HID + (h - NHEADS) * HDIM;
    const float scale = isQ ? 0.125f * 1.4426950408889634f : 1.0f;

    const float* src = g_QKf + (size_t)s * QKW + base;
    __half* dst = g_QKh + (size_t)s * QKW + base;

    float x1 = src[i];
    float x2 = src[i + 32];
    const float LN10000 = 9.210340371976184f;
    float inv = expf(-(float)i * (LN10000 / 32.0f));
    float ang = (float)s * inv;
    float c, sn;
    sincosf(ang, &sn, &c);
    dst[pmap32(i)]      = __float2half_rn((x1 * c - x2 * sn) * scale);
    dst[pmap32(i + 32)] = __float2half_rn((x2 * c + x1 * sn) * scale);
}

// ---------------------------------------------------------------------------
// fp16 tensor-core causal GQA flash attention (no-max softmax, base-2).
// R12 scheduling: one qb per CTA, 512 CTAs, heavy-first (dynamic backfill).
// V token-pair interleaved in g_Vt -> PV B-loads conflict-free LDS.64.
// ---------------------------------------------------------------------------
#define ATT_Q_UNITS  (128 * 32)
#define ATT_KV_UNITS (64 * 32)
#define ATT_SMEM_BYTES ((ATT_Q_UNITS + 4 * ATT_KV_UNITS) * 4)

__device__ __forceinline__ void attn_issue_kv(uint32_t* Kd, uint32_t* Vd,
                                              int k0, int kvh, int tid)
{
    const int lr = tid >> 2;
    const int jb = (tid & 3) * 2;
    const __half* kg = g_QKh + (size_t)(k0 + lr) * QKW + HID + kvh * HDIM;
    const __half* vg = g_Vt + (size_t)(kvh * HDIM + lr) * S_LEN + k0;
    uint32_t kd = smem_u32(Kd + lr * 32);
    uint32_t vd = smem_u32(Vd + lr * 32);
    const uint32_t sw = (lr & 3) << 3;
#pragma unroll
    for (int e = 0; e < 2; e++) {
        const int j = jb + e;
        const uint32_t u = (((uint32_t)(4 * j)) ^ sw) * 4;
        CP_ASYNC16(kd + u, kg + j * 8);
        CP_ASYNC16(vd + u, vg + j * 8);
    }
}

__global__ __launch_bounds__(256, 2) void attn_mma()
{
    extern __shared__ uint32_t smu[];
    uint32_t* Qs  = smu;
    uint32_t* Kb0 = smu + ATT_Q_UNITS;
    uint32_t* Kb1 = Kb0 + ATT_KV_UNITS;
    uint32_t* Vb0 = Kb1 + ATT_KV_UNITS;
    uint32_t* Vb1 = Vb0 + ATT_KV_UNITS;

    const int head = blockIdx.x;
    const int qb   = (gridDim.y - 1) - blockIdx.y;   // heavy CTAs first
    const int kvh  = head % KVHEADS;
    const int q0   = qb * 128;
    const int tid  = threadIdx.x;
    const int wid  = tid >> 5;
    const int lane = tid & 31;
    const int g = lane >> 2, q = lane & 3;
    const int wm = wid * 16;
    const int fsw = (g & 3) << 3;

    const int T = 2 * qb + 2;
    attn_issue_kv(Kb0, Vb0, 0, kvh, tid);
    CP_COMMIT();

    // Q tile (128 x 64 halves) -> Qs (interleaved by rope; swizzled here)
    {
        const int r  = tid >> 1;
        const int s0 = (tid & 1) * 4;
        const int sw = (r & 3) << 3;
        const __half* src = g_QKh + (size_t)(q0 + r) * QKW + head * HDIM + (tid & 1) * 32;
        uint32_t* dst = Qs + r * 32;
#pragma unroll
        for (int j = 0; j < 4; j++) {
            const uint4 v = *(const uint4*)(src + j * 8);
            *(uint4*)(dst + (((s0 + j) * 4) ^ sw)) = v;
        }
    }
    __syncthreads();

    uint32_t qf[4][4];
#pragma unroll
    for (int ks = 0; ks < 4; ks++) {
        const int scol = ((ks * 8) ^ fsw) + 2 * q;
        const uint32_t* a = Qs + (wm + g) * 32 + scol;
        const uint2 vlo = *(const uint2*)a;
        const uint2 vhi = *(const uint2*)(a + 8 * 32);
        qf[ks][0] = vlo.x; qf[ks][1] = vhi.x;
        qf[ks][2] = vlo.y; qf[ks][3] = vhi.y;
    }

    float o[8][4];
#pragma unroll
    for (int nf = 0; nf < 8; nf++)
#pragma unroll
        for (int j = 0; j < 4; j++) o[nf][j] = 0.f;
    float l0 = 0.f, l1 = 0.f;

    for (int t = 0; t < T; t++) {
        if (t + 1 < T) {
            attn_issue_kv(((t + 1) & 1) ? Kb1 : Kb0, ((t + 1) & 1) ? Vb1 : Vb0,
                          (t + 1) * 64, kvh, tid);
            CP_COMMIT();
            CP_WAIT(1);
        } else {
            CP_WAIT(0);
        }
        __syncthreads();

        const int k0 = t * 64;
        const bool active = (k0 <= q0 + wm + 15);   // warp-uniform

        if (active) {
            const uint32_t* Ks = (t & 1) ? Kb1 : Kb0;
            const uint32_t* Vs = (t & 1) ? Vb1 : Vb0;

            // ---- S = Q K^T (base-2 log domain) ----
            float s[8][4];
#pragma unroll
            for (int nf = 0; nf < 8; nf++)
#pragma unroll
                for (int j = 0; j < 4; j++) s[nf][j] = 0.f;

#pragma unroll
            for (int ks = 0; ks < 4; ks++) {
                const int scol = ((ks * 8) ^ fsw) + 2 * q;
#pragma unroll
                for (int nf = 0; nf < 8; nf++) {
                    const uint2 vb = *(const uint2*)(Ks + (nf * 8 + g) * 32 + scol);
                    mma_f16(s[nf], qf[ks], vb.x, vb.y);
                }
            }

            // ---- causal mask ----
            if (k0 + 63 > q0 + wm) {
                const int row0 = q0 + wm + g;
#pragma unroll
                for (int nf = 0; nf < 8; nf++) {
                    const int c = k0 + nf * 8 + 2 * q;
                    if (c     > row0)     s[nf][0] = -1e30f;
                    if (c + 1 > row0)     s[nf][1] = -1e30f;
                    if (c     > row0 + 8) s[nf][2] = -1e30f;
                    if (c + 1 > row0 + 8) s[nf][3] = -1e30f;
                }
            }

            // ---- softmax numerator: raw ex2 ----
            float rs0 = 0.f, rs1 = 0.f;
#pragma unroll
            for (int nf = 0; nf < 8; nf++) {
                s[nf][0] = fexp2(s[nf][0]);
                s[nf][1] = fexp2(s[nf][1]);
                s[nf][2] = fexp2(s[nf][2]);
                s[nf][3] = fexp2(s[nf][3]);
                rs0 += s[nf][0] + s[nf][1];
                rs1 += s[nf][2] + s[nf][3];
            }
            rs0 += __shfl_xor_sync(0xffffffffu, rs0, 1);
            rs0 += __shfl_xor_sync(0xffffffffu, rs0, 2);
            rs1 += __shfl_xor_sync(0xffffffffu, rs1, 1);
            rs1 += __shfl_xor_sync(0xffffffffu, rs1, 2);
            l0 += rs0;
            l1 += rs1;

            // ---- O += P V : token-interleaved V -> LDS.64 B frags ----
#pragma unroll
            for (int kb = 0; kb < 4; kb++) {
                uint32_t pa[4];
                pa[0] = pack_h2(s[2 * kb][0],     s[2 * kb][1]);
                pa[1] = pack_h2(s[2 * kb][2],     s[2 * kb][3]);
                pa[2] = pack_h2(s[2 * kb + 1][0], s[2 * kb + 1][1]);
                pa[3] = pack_h2(s[2 * kb + 1][2], s[2 * kb + 1][3]);
                const int vcol = ((8 * kb) ^ fsw) + 2 * q;
#pragma unroll
                for (int nf = 0; nf < 8; nf++) {
                    const uint2 vb = *(const uint2*)(Vs + (nf * 8 + g) * 32 + vcol);
                    mma_f16(o[nf], pa, vb.x, vb.y);
                }
            }
        }
        __syncthreads();
    }

    // ---- epilogue: normalize, write g_Ah interleaved ----
    const float inv0 = 1.f / l0;
    const float inv1 = 1.f / l1;
    const int row0 = q0 + wm + g;
    half2* Ah2 = (half2*)g_Ah;
#pragma unroll
    for (int nf = 0; nf < 8; nf++) {
        const int jj = 4 * nf + q;
        const int pos = head * 32 + ((jj & ~7) | p8(jj & 7));
        Ah2[(size_t)row0 * (HID / 2) + pos] =
            __floats2half2_rn(o[nf][0] * inv0, o[nf][1] * inv0);
        Ah2[(size_t)(row0 + 8) * (HID / 2) + pos] =
            __floats2half2_rn(o[nf][2] * inv1, o[nf][3] * inv1);
    }
}

// ---------------------------------------------------------------------------
extern "C" void kernel_launch(void* const* d_in, const int* in_sizes, int n_in,
                              void* d_out, int out_size)
{
    const float* hs = (const float*)d_in[0];
    const float* Wq = (const float*)d_in[1];
    const float* Wk = (const float*)d_in[2];
    const float* Wv = (const float*)d_in[3];
    const float* Wo = (const float*)d_in[4];
    float* out = (float*)d_out;

    __half *Ah, *WoTh;
    cudaGetSymbolAddress((void**)&Ah, g_Ah);
    cudaGetSymbolAddress((void**)&WoTh, g_WoTh);

    cudaFuncSetAttribute(mma_gemm_qkv, cudaFuncAttributeMaxDynamicSharedMemorySize,
                         QGEMM_SMEM_BYTES);
    cudaFuncSetAttribute(mma_gemm, cudaFuncAttributeMaxDynamicSharedMemorySize,
                         GEMM_SMEM_BYTES);
    cudaFuncSetAttribute(attn_mma, cudaFuncAttributeMaxDynamicSharedMemorySize,
                         ATT_SMEM_BYTES);

    // Prep: weights -> half transposed interleaved; hs -> half interleaved
    prep_all<<<dim3(64, 64, 5), dim3(32, 8)>>>(hs, Wq, Wk, Wv, Wo);

    // Fused QKV projection: Q|K -> fp32, V -> Vt half (token-interleaved)
    mma_gemm_qkv<<<dim3(QKVW / 192, S_LEN / 128), 512, QGEMM_SMEM_BYTES>>>();

    // RoPE: fp32 -> half interleaved (Q pre-scaled by log2e/8)
    rope_kernel<<<dim3(S_LEN, 5), 256>>>();

    // fp16 tensor-core causal attention (heavy-first, dynamic backfill)
    attn_mma<<<dim3(NHEADS, S_LEN / 128), 256, ATT_SMEM_BYTES>>>();

    // Output projection (fp32 out)
    mma_gemm<<<dim3(HID / 128, S_LEN / 128), 256, GEMM_SMEM_BYTES>>>(
        Ah, WoTh, out, S_LEN, HID, HID);
}

// round 15
// speedup vs baseline: 1.1876x; 1.1289x over previous
#include <cuda_runtime.h>
#include <cuda_fp16.h>
#include <cstdint>

#define S_LEN   2048
#define HID     2048
#define NHEADS  32
#define KVHEADS 8
#define HDIM    64
#define KVW     (KVHEADS * HDIM)   // 512
#define QKVW    (HID + 2 * KVW)    // 3072
#define QKW     (HID + KVW)        // 2560 (Q|K region width)

// ---------------- scratch (__device__ globals; no allocs allowed) ----------
__device__ __align__(16) __half g_HSh[S_LEN * HID];    // hs, half, plain
__device__ __align__(16) __half g_WTh[QKVW * HID];     // WqT|WkT|WvT [N,K] plain
__device__ __align__(16) __half g_WoTh[HID * HID];     // WoT [N,K] plain
__device__ __align__(16) float  g_QKf[S_LEN * QKW];    // Q|K fp32 (pre-rope)
__device__ __align__(16) __half g_QKh[S_LEN * QKW];    // Q|K half, plain
__device__ __align__(16) __half g_Vt[KVW * S_LEN];     // V^T [feature][token], plain
__device__ __align__(16) __half g_Ah[S_LEN * HID];     // attn out, plain

// ---------------- helpers ---------------------------------------------------
__device__ __forceinline__ uint32_t smem_u32(const void* p) {
    uint32_t a;
    asm("{ .reg .u64 t; cvta.to.shared.u64 t, %1; cvt.u32.u64 %0, t; }" : "=r"(a) : "l"(p));
    return a;
}
__device__ __forceinline__ uint32_t pack_h2(float lo, float hi) {
    uint32_t r;
    asm("cvt.rn.f16x2.f32 %0, %1, %2;" : "=r"(r) : "f"(hi), "f"(lo));
    return r;
}
__device__ __forceinline__ float fexp2(float x) {
    float y;
    asm("ex2.approx.f32 %0, %1;" : "=f"(y) : "f"(x));
    return y;
}
__device__ __forceinline__ void ldsm4(uint32_t* r, uint32_t a) {
    asm volatile("ldmatrix.sync.aligned.m8n8.x4.shared.b16 {%0,%1,%2,%3}, [%4];"
        : "=r"(r[0]), "=r"(r[1]), "=r"(r[2]), "=r"(r[3]) : "r"(a));
}
__device__ __forceinline__ void mma_f16(float* d, const uint32_t* a,
                                        uint32_t b0, uint32_t b1) {
    asm volatile("mma.sync.aligned.m16n8k16.row.col.f32.f16.f16.f32 "
        "{%0,%1,%2,%3}, {%4,%5,%6,%7}, {%8,%9}, {%0,%1,%2,%3};"
        : "+f"(d[0]), "+f"(d[1]), "+f"(d[2]), "+f"(d[3])
        : "r"(a[0]), "r"(a[1]), "r"(a[2]), "r"(a[3]), "r"(b0), "r"(b1));
}
#define CP_ASYNC16(dst, src) \
    asm volatile("cp.async.cg.shared.global [%0], [%1], 16;" :: "r"(dst), "l"(src) : "memory")
#define CP_COMMIT()  asm volatile("cp.async.commit_group;" ::: "memory")
#define CP_WAIT(n)   asm volatile("cp.async.wait_group %0;" :: "n"(n) : "memory")

#define NSTAGE 3
// SMEM geometry: rows of 64 halves = 128 bytes = 8 chunks of 16B.
// Swizzle: chunk' = chunk ^ (row & 7)  (full 8-way; LDSM phases conflict-free).

// ---------------------------------------------------------------------------
// QKV GEMM: 512 threads, CTA tile 128x192, warp 32x48, grid 256 CTAs.
// Output: cols < QKW -> g_QKf fp32; cols >= QKW -> g_Vt (plain).
// ---------------------------------------------------------------------------
#define QSTAGE_BYTES ((128 + 192) * 128)
#define QGEMM_SMEM_BYTES (NSTAGE * QSTAGE_BYTES)

__device__ __forceinline__ void qkv_issue_stage(uint32_t sb, int m0, int n0,
                                                int kc, int buf, int tid)
{
    const uint32_t St = sb + buf * QSTAGE_BYTES;
#pragma unroll
    for (int t = 0; t < 5; t++) {
        const int cid = tid + t * 512;       // 0..2559
        const int row = cid >> 3;            // 0..319
        const int j   = cid & 7;
        const uint32_t cc = (uint32_t)(j ^ (row & 7));
        const __half* src = (row < 128)
            ? g_HSh + (size_t)(m0 + row) * HID + kc * 64 + j * 8
            : g_WTh + (size_t)(n0 + row - 128) * HID + kc * 64 + j * 8;
        CP_ASYNC16(St + row * 128 + cc * 16, src);
    }
}

__global__ __launch_bounds__(512) void mma_gemm_qkv()
{
    extern __shared__ uint32_t smu[];
    const uint32_t sb = smem_u32(smu);
    const int tid  = threadIdx.x;
    const int wid  = tid >> 5;
    const int lane = tid & 31;
    const int g = lane >> 2;
    const int q = lane & 3;
    const int jj = lane >> 3;
    const int rr = lane & 7;
    const int m0 = blockIdx.y * 128;
    const int n0 = blockIdx.x * 192;
    const int wm = (wid & 3) * 32;
    const int wn = (wid >> 2) * 48;

    // LDSM lane rows (fixed per thread)
    const int arow = wm + rr + (jj & 1) * 8;            // A-operand lane row
    const int asw  = arow & 7;
    const int brow = wn + rr + (jj >> 1) * 8;           // B-operand lane row
    const int bsw  = brow & 7;
    const int ajh  = jj >> 1;                           // A chunk sub-index
    const int bjl  = jj & 1;                            // B chunk sub-index

    float acc[2][6][4];
#pragma unroll
    for (int i = 0; i < 2; i++)
#pragma unroll
        for (int j = 0; j < 6; j++)
#pragma unroll
            for (int k = 0; k < 4; k++) acc[i][j][k] = 0.f;

    const int nch = HID / 64;   // 32
    qkv_issue_stage(sb, m0, n0, 0, 0, tid);
    CP_COMMIT();
    qkv_issue_stage(sb, m0, n0, 1, 1, tid);
    CP_COMMIT();

    int buf = 0;
    for (int kc = 0; kc < nch; kc++) {
        if (kc + 1 < nch) { CP_WAIT(1); } else { CP_WAIT(0); }
        __syncthreads();

        const uint32_t sbA = sb + buf * QSTAGE_BYTES;
        const uint32_t aAdr = sbA + arow * 128;
        const uint32_t bAdr = sbA + 128 * 128 + brow * 128;

#pragma unroll
        for (int ks = 0; ks < 4; ks++) {
            const uint32_t ca = (uint32_t)((ks * 2 + ajh) ^ asw) * 16;
            const uint32_t cb = (uint32_t)((ks * 2 + bjl) ^ bsw) * 16;
            uint32_t af[2][4];
            ldsm4(af[0], aAdr + ca);
            ldsm4(af[1], aAdr + 2048 + ca);
            uint32_t bf[6][2];
#pragma unroll
            for (int np = 0; np < 3; np++) {
                uint32_t t4[4];
                ldsm4(t4, bAdr + np * 2048 + cb);
                bf[2 * np][0] = t4[0];     bf[2 * np][1] = t4[1];
                bf[2 * np + 1][0] = t4[2]; bf[2 * np + 1][1] = t4[3];
            }
#pragma unroll
            for (int fm = 0; fm < 2; fm++)
#pragma unroll
                for (int fn = 0; fn < 6; fn++)
                    mma_f16(acc[fm][fn], af[fm], bf[fn][0], bf[fn][1]);
        }

        if (kc + 2 < nch) {
            const int nb = (buf + 2 >= NSTAGE) ? buf + 2 - NSTAGE : buf + 2;
            qkv_issue_stage(sb, m0, n0, kc + 2, nb, tid);
            CP_COMMIT();
        }
        buf = (buf + 1 == NSTAGE) ? 0 : buf + 1;
    }

#pragma unroll
    for (int fm = 0; fm < 2; fm++) {
        const int r0 = m0 + wm + fm * 16 + g;
#pragma unroll
        for (int fn = 0; fn < 6; fn++) {
            const int c = n0 + wn + fn * 8 + 2 * q;
            if (c >= QKW) {   // V region: transposed halves (plain token order)
                const int vr = c - QKW;
                g_Vt[(size_t)vr * S_LEN + r0]           = __float2half_rn(acc[fm][fn][0]);
                g_Vt[(size_t)(vr + 1) * S_LEN + r0]     = __float2half_rn(acc[fm][fn][1]);
                g_Vt[(size_t)vr * S_LEN + r0 + 8]       = __float2half_rn(acc[fm][fn][2]);
                g_Vt[(size_t)(vr + 1) * S_LEN + r0 + 8] = __float2half_rn(acc[fm][fn][3]);
            } else {          // Q|K region: fp32 (rope consumes)
                *(float2*)(g_QKf + (size_t)r0 * QKW + c) =
                    make_float2(acc[fm][fn][0], acc[fm][fn][1]);
                *(float2*)(g_QKf + (size_t)(r0 + 8) * QKW + c) =
                    make_float2(acc[fm][fn][2], acc[fm][fn][3]);
            }
        }
    }
}

// ---------------------------------------------------------------------------
// Wo GEMM: 256 threads, CTA 128x128, warp 64x32, LDSM fragments.
// ---------------------------------------------------------------------------
#define STAGE_BYTES (2 * 128 * 128)
#define GEMM_SMEM_BYTES (NSTAGE * STAGE_BYTES)

__device__ __forceinline__ void gemm_issue_stage(const __half* A, const __half* Bt,
                                                 uint32_t sb, int m0, int n0, int Kh,
                                                 int kc, int buf, int lrow, int lsel)
{
    const uint32_t St = sb + buf * STAGE_BYTES;
    const __half* Ap = A  + (size_t)(m0 + lrow) * Kh + kc * 64 + lsel * 32;
    const __half* Bp = Bt + (size_t)(n0 + lrow) * Kh + kc * 64 + lsel * 32;
    const uint32_t da = St + lrow * 128;
    const uint32_t db = da + 128 * 128;
    const int sw = lrow & 7;
#pragma unroll
    for (int j = 0; j < 4; j++) {
        const uint32_t cc = (uint32_t)((lsel * 4 + j) ^ sw) * 16;
        CP_ASYNC16(da + cc, Ap + j * 8);
        CP_ASYNC16(db + cc, Bp + j * 8);
    }
}

__global__ __launch_bounds__(256) void mma_gemm(const __half* __restrict__ A,
                                                const __half* __restrict__ Bt,
                                                float* __restrict__ Cf,
                                                int M, int N, int Kh)
{
    extern __shared__ uint32_t smu[];
    const uint32_t sb = smem_u32(smu);
    const int tid  = threadIdx.x;
    const int wid  = tid >> 5;
    const int lane = tid & 31;
    const int g = lane >> 2;
    const int q = lane & 3;
    const int jj = lane >> 3;
    const int rr = lane & 7;
    const int m0 = blockIdx.y * 128;
    const int n0 = blockIdx.x * 128;
    const int wm = (wid & 1) * 64;
    const int wn = (wid >> 1) * 32;

    const int lrow = tid >> 1;
    const int lsel = tid & 1;

    const int arow = wm + rr + (jj & 1) * 8;
    const int asw  = arow & 7;
    const int brow = wn + rr + (jj >> 1) * 8;
    const int bsw  = brow & 7;
    const int ajh  = jj >> 1;
    const int bjl  = jj & 1;

    float acc[4][4][4];
#pragma unroll
    for (int i = 0; i < 4; i++)
#pragma unroll
        for (int j = 0; j < 4; j++)
#pragma unroll
            for (int k = 0; k < 4; k++) acc[i][j][k] = 0.f;

    const int nch = Kh / 64;
    gemm_issue_stage(A, Bt, sb, m0, n0, Kh, 0, 0, lrow, lsel);
    CP_COMMIT();
    if (nch > 1) {
        gemm_issue_stage(A, Bt, sb, m0, n0, Kh, 1, 1, lrow, lsel);
        CP_COMMIT();
    }

    int buf = 0;
    for (int kc = 0; kc < nch; kc++) {
        if (kc + 1 < nch) { CP_WAIT(1); } else { CP_WAIT(0); }
        __syncthreads();

        const uint32_t sbA = sb + buf * STAGE_BYTES;
        const uint32_t aAdr = sbA + arow * 128;
        const uint32_t bAdr = sbA + 128 * 128 + brow * 128;

#pragma unroll
        for (int ks = 0; ks < 4; ks++) {
            const uint32_t ca = (uint32_t)((ks * 2 + ajh) ^ asw) * 16;
            const uint32_t cb = (uint32_t)((ks * 2 + bjl) ^ bsw) * 16;
            uint32_t af[4][4];
#pragma unroll
            for (int fm = 0; fm < 4; fm++)
                ldsm4(af[fm], aAdr + fm * 2048 + ca);
            uint32_t bf[4][2];
#pragma unroll
            for (int np = 0; np < 2; np++) {
                uint32_t t4[4];
                ldsm4(t4, bAdr + np * 2048 + cb);
                bf[2 * np][0] = t4[0];     bf[2 * np][1] = t4[1];
                bf[2 * np + 1][0] = t4[2]; bf[2 * np + 1][1] = t4[3];
            }
#pragma unroll
            for (int fm = 0; fm < 4; fm++)
#pragma unroll
                for (int fn = 0; fn < 4; fn++)
                    mma_f16(acc[fm][fn], af[fm], bf[fn][0], bf[fn][1]);
        }

        if (kc + 2 < nch) {
            const int nb = (buf + 2 >= NSTAGE) ? buf + 2 - NSTAGE : buf + 2;
            gemm_issue_stage(A, Bt, sb, m0, n0, Kh, kc + 2, nb, lrow, lsel);
            CP_COMMIT();
        }
        buf = (buf + 1 == NSTAGE) ? 0 : buf + 1;
    }

#pragma unroll
    for (int fm = 0; fm < 4; fm++) {
        const int r0 = m0 + wm + fm * 16 + g;
#pragma unroll
        for (int fn = 0; fn < 4; fn++) {
            const int c = n0 + wn + fn * 8 + 2 * q;
            *(float2*)(Cf + (size_t)r0 * N + c) =
                make_float2(acc[fm][fn][0], acc[fm][fn][1]);
            *(float2*)(Cf + (size_t)(r0 + 8) * N + c) =
                make_float2(acc[fm][fn][2], acc[fm][fn][3]);
        }
    }
}

// ---------------------------------------------------------------------------
// Fused prep: weight transposes (half, plain) + hs -> half (plain).
// ---------------------------------------------------------------------------
__global__ void prep_all(const float* __restrict__ hs,
                         const float* __restrict__ Wq, const float* __restrict__ Wk,
                         const float* __restrict__ Wv, const float* __restrict__ Wo)
{
    __shared__ float t[32][33];
    const int z = blockIdx.z;
    const int x = threadIdx.x, y = threadIdx.y;
    const int bx = blockIdx.x * 32;
    const int by = blockIdx.y * 32;

    if (z == 4) {
        const float* src = hs + (size_t)by * HID + bx;
        __half* dst = g_HSh + (size_t)by * HID + bx;
#pragma unroll
        for (int i = 0; i < 32; i += 8)
            dst[(size_t)(y + i) * HID + x] = __float2half_rn(src[(size_t)(y + i) * HID + x]);
        return;
    }

    const float* src;
    __half* dst;
    int C;
    if (z == 0)      { src = Wq; dst = g_WTh;                              C = HID; }
    else if (z == 1) { src = Wo; dst = g_WoTh;                             C = HID; }
    else if (z == 2) { src = Wk; dst = g_WTh + (size_t)HID * HID;          C = KVW; }
    else             { src = Wv; dst = g_WTh + (size_t)(HID + KVW) * HID;  C = KVW; }
    if (bx >= C) return;

#pragma unroll
    for (int i = 0; i < 32; i += 8)
        t[y + i][x] = src[(size_t)(by + y + i) * C + bx + x];
    __syncthreads();
#pragma unroll
    for (int i = 0; i < 32; i += 8)
        dst[(size_t)(bx + y + i) * HID + by + x] = __float2half_rn(t[x][y + i]);
}

// ---------------------------------------------------------------------------
// RoPE: g_QKf (fp32) -> g_QKh (half, plain). Q scale = log2(e)/8.
// ---------------------------------------------------------------------------
__global__ __launch_bounds__(256) void rope_kernel()
{
    const int s = blockIdx.x;
    const int w = threadIdx.x >> 5;
    const int i = threadIdx.x & 31;
    const int h = blockIdx.y * 8 + w;      // 0..39

    const bool isQ = (h < NHEADS);
    const int base = isQ ? h * HDIM : HID + (h - NHEADS) * HDIM;
    const float scale = isQ ? 0.125f * 1.4426950408889634f : 1.0f;

    const float* src = g_QKf + (size_t)s * QKW + base;
    __half* dst = g_QKh + (size_t)s * QKW + base;

    float x1 = src[i];
    float x2 = src[i + 32];
    const float LN10000 = 9.210340371976184f;
    float inv = expf(-(float)i * (LN10000 / 32.0f));
    float ang = (float)s * inv;
    float c, sn;
    sincosf(ang, &sn, &c);
    dst[i]      = __float2half_rn((x1 * c - x2 * sn) * scale);
    dst[i + 32] = __float2half_rn((x2 * c + x1 * sn) * scale);
}

// ---------------------------------------------------------------------------
// fp16 tensor-core causal GQA flash attention (no-max softmax, base-2).
// One qb per CTA, 512 CTAs, heavy-first. All fragment loads via LDSM.
// ---------------------------------------------------------------------------
#define ATT_Q_BYTES  (128 * 128)
#define ATT_KV_BYTES (64 * 128)
#define ATT_SMEM_BYTES (ATT_Q_BYTES + 4 * ATT_KV_BYTES)

__device__ __forceinline__ void attn_issue_kv(uint32_t kd, uint32_t vd,
                                              int k0, int kvh, int tid)
{
    const int lr = tid >> 2;
    const int jb = (tid & 3) * 2;
    const __half* kg = g_QKh + (size_t)(k0 + lr) * QKW + HID + kvh * HDIM;
    const __half* vg = g_Vt + (size_t)(kvh * HDIM + lr) * S_LEN + k0;
    const int sw = lr & 7;
    kd += lr * 128;
    vd += lr * 128;
#pragma unroll
    for (int e = 0; e < 2; e++) {
        const int j = jb + e;
        const uint32_t cc = (uint32_t)(j ^ sw) * 16;
        CP_ASYNC16(kd + cc, kg + j * 8);
        CP_ASYNC16(vd + cc, vg + j * 8);
    }
}

__global__ __launch_bounds__(256, 2) void attn_mma()
{
    extern __shared__ uint32_t smu[];
    const uint32_t sb  = smem_u32(smu);
    const uint32_t sbQ = sb;
    const uint32_t sbK0 = sb + ATT_Q_BYTES;
    const uint32_t sbK1 = sbK0 + ATT_KV_BYTES;
    const uint32_t sbV0 = sbK1 + ATT_KV_BYTES;
    const uint32_t sbV1 = sbV0 + ATT_KV_BYTES;

    const int head = blockIdx.x;
    const int qb   = (gridDim.y - 1) - blockIdx.y;   // heavy CTAs first
    const int kvh  = head % KVHEADS;
    const int q0   = qb * 128;
    const int tid  = threadIdx.x;
    const int wid  = tid >> 5;
    const int lane = tid & 31;
    const int g = lane >> 2, q = lane & 3;
    const int jj = lane >> 3, rr = lane & 7;
    const int wm = wid * 16;

    const int arow = wm + rr + (jj & 1) * 8;   // Q lane row
    const int asw  = arow & 7;
    const int brow = rr + (jj >> 1) * 8;       // K/V lane row (base)
    const int bsw  = brow & 7;
    const int ajh  = jj >> 1;
    const int bjl  = jj & 1;

    const int T = 2 * qb + 2;
    attn_issue_kv(sbK0, sbV0, 0, kvh, tid);
    CP_COMMIT();

    // Q tile (128 x 64 halves) -> Qs, plain order, swizzled chunks
    {
        const int r  = tid >> 1;
        const int sw = r & 7;
        const __half* src = g_QKh + (size_t)(q0 + r) * QKW + head * HDIM + (tid & 1) * 32;
        const uint32_t dst = sbQ + r * 128;
#pragma unroll
        for (int j = 0; j < 4; j++) {
            const uint32_t cc = (uint32_t)(((tid & 1) * 4 + j) ^ sw) * 16;
            // plain copy (no cvt needed): 16B via cp.async would race with
            // the K/V group bookkeeping; use direct st since src is in L2
            *(uint4*)(uint64_t)0; // placeholder removed below
        }
    }
    // NOTE: the placeholder above is unreachable; real Q copy below.
    {
        const int r  = tid >> 1;
        const int sw = r & 7;
        const __half* src = g_QKh + (size_t)(q0 + r) * QKW + head * HDIM + (tid & 1) * 32;
        // write via standard stores (Qs read only after __syncthreads)
        uint32_t dst = sbQ + r * 128;
#pragma unroll
        for (int j = 0; j < 4; j++) {
            const uint4 v = *(const uint4*)(src + j * 8);
            const uint32_t cc = (uint32_t)(((tid & 1) * 4 + j) ^ sw) * 16;
            asm volatile("st.shared.v4.b32 [%0], {%1,%2,%3,%4};"
                :: "r"(dst + cc), "r"(v.x), "r"(v.y), "r"(v.z), "r"(v.w) : "memory");
        }
    }
    __syncthreads();

    uint32_t qf[4][4];
#pragma unroll
    for (int ks = 0; ks < 4; ks++) {
        const uint32_t ca = (uint32_t)((ks * 2 + ajh) ^ asw) * 16;
        ldsm4(qf[ks], sbQ + arow * 128 + ca);
    }

    float o[8][4];
#pragma unroll
    for (int nf = 0; nf < 8; nf++)
#pragma unroll
        for (int j = 0; j < 4; j++) o[nf][j] = 0.f;
    float l0 = 0.f, l1 = 0.f;

    for (int t = 0; t < T; t++) {
        if (t + 1 < T) {
            attn_issue_kv(((t + 1) & 1) ? sbK1 : sbK0, ((t + 1) & 1) ? sbV1 : sbV0,
                          (t + 1) * 64, kvh, tid);
            CP_COMMIT();
            CP_WAIT(1);
        } else {
            CP_WAIT(0);
        }
        __syncthreads();

        const int k0 = t * 64;
        const bool active = (k0 <= q0 + wm + 15);   // warp-uniform

        if (active) {
            const uint32_t kAdr = ((t & 1) ? sbK1 : sbK0) + brow * 128;
            const uint32_t vAdr = ((t & 1) ? sbV1 : sbV0) + brow * 128;

            // ---- S = Q K^T (base-2 log domain) ----
            float s[8][4];
#pragma unroll
            for (int nf = 0; nf < 8; nf++)
#pragma unroll
                for (int j = 0; j < 4; j++) s[nf][j] = 0.f;

#pragma unroll
            for (int ks = 0; ks < 4; ks++) {
                const uint32_t cb = (uint32_t)((ks * 2 + bjl) ^ bsw) * 16;
#pragma unroll
                for (int np = 0; np < 4; np++) {
                    uint32_t t4[4];
                    ldsm4(t4, kAdr + np * 2048 + cb);
                    mma_f16(s[2 * np],     qf[ks], t4[0], t4[1]);
                    mma_f16(s[2 * np + 1], qf[ks], t4[2], t4[3]);
                }
            }

            // ---- causal mask ----
            if (k0 + 63 > q0 + wm) {
                const int row0 = q0 + wm + g;
#pragma unroll
                for (int nf = 0; nf < 8; nf++) {
                    const int c = k0 + nf * 8 + 2 * q;
                    if (c     > row0)     s[nf][0] = -1e30f;
                    if (c + 1 > row0)     s[nf][1] = -1e30f;
                    if (c     > row0 + 8) s[nf][2] = -1e30f;
                    if (c + 1 > row0 + 8) s[nf][3] = -1e30f;
                }
            }

            // ---- softmax numerator: raw ex2 ----
            float rs0 = 0.f, rs1 = 0.f;
#pragma unroll
            for (int nf = 0; nf < 8; nf++) {
                s[nf][0] = fexp2(s[nf][0]);
                s[nf][1] = fexp2(s[nf][1]);
                s[nf][2] = fexp2(s[nf][2]);
                s[nf][3] = fexp2(s[nf][3]);
                rs0 += s[nf][0] + s[nf][1];
                rs1 += s[nf][2] + s[nf][3];
            }
            rs0 += __shfl_xor_sync(0xffffffffu, rs0, 1);
            rs0 += __shfl_xor_sync(0xffffffffu, rs0, 2);
            rs1 += __shfl_xor_sync(0xffffffffu, rs1, 1);
            rs1 += __shfl_xor_sync(0xffffffffu, rs1, 2);
            l0 += rs0;
            l1 += rs1;

            // ---- O += P V : P frags from accumulators; V via LDSM ----
#pragma unroll
            for (int kb = 0; kb < 4; kb++) {
                uint32_t pa[4];
                pa[0] = pack_h2(s[2 * kb][0],     s[2 * kb][1]);
                pa[1] = pack_h2(s[2 * kb][2],     s[2 * kb][3]);
                pa[2] = pack_h2(s[2 * kb + 1][0], s[2 * kb + 1][1]);
                pa[3] = pack_h2(s[2 * kb + 1][2], s[2 * kb + 1][3]);
                const uint32_t cv = (uint32_t)((kb * 2 + bjl) ^ bsw) * 16;
#pragma unroll
                for (int np = 0; np < 4; np++) {
                    uint32_t t4[4];
                    ldsm4(t4, vAdr + np * 2048 + cv);
                    mma_f16(o[2 * np],     pa, t4[0], t4[1]);
                    mma_f16(o[2 * np + 1], pa, t4[2], t4[3]);
                }
            }
        }
        __syncthreads();
    }

    // ---- epilogue: normalize, write g_Ah plain ----
    const float inv0 = 1.f / l0;
    const float inv1 = 1.f / l1;
    const int row0 = q0 + wm + g;
    half2* Ah2 = (half2*)g_Ah;
#pragma unroll
    for (int nf = 0; nf < 8; nf++) {
        const int pos = head * 32 + 4 * nf + q;
        Ah2[(size_t)row0 * (HID / 2) + pos] =
            __floats2half2_rn(o[nf][0] * inv0, o[nf][1] * inv0);
        Ah2[(size_t)(row0 + 8) * (HID / 2) + pos] =
            __floats2half2_rn(o[nf][2] * inv1, o[nf][3] * inv1);
    }
}

// ---------------------------------------------------------------------------
extern "C" void kernel_launch(void* const* d_in, const int* in_sizes, int n_in,
                              void* d_out, int out_size)
{
    const float* hs = (const float*)d_in[0];
    const float* Wq = (const float*)d_in[1];
    const float* Wk = (const float*)d_in[2];
    const float* Wv = (const float*)d_in[3];
    const float* Wo = (const float*)d_in[4];
    float* out = (float*)d_out;

    __half *Ah, *WoTh;
    cudaGetSymbolAddress((void**)&Ah, g_Ah);
    cudaGetSymbolAddress((void**)&WoTh, g_WoTh);

    cudaFuncSetAttribute(mma_gemm_qkv, cudaFuncAttributeMaxDynamicSharedMemorySize,
                         QGEMM_SMEM_BYTES);
    cudaFuncSetAttribute(mma_gemm, cudaFuncAttributeMaxDynamicSharedMemorySize,
                         GEMM_SMEM_BYTES);
    cudaFuncSetAttribute(attn_mma, cudaFuncAttributeMaxDynamicSharedMemorySize,
                         ATT_SMEM_BYTES);

    // Prep: weights -> half transposed (plain); hs -> half (plain)
    prep_all<<<dim3(64, 64, 5), dim3(32, 8)>>>(hs, Wq, Wk, Wv, Wo);

    // Fused QKV projection: Q|K -> fp32, V -> Vt half
    mma_gemm_qkv<<<dim3(QKVW / 192, S_LEN / 128), 512, QGEMM_SMEM_BYTES>>>();

    // RoPE: fp32 -> half (Q pre-scaled by log2e/8)
    rope_kernel<<<dim3(S_LEN, 5), 256>>>();

    // fp16 tensor-core causal attention (LDSM fragments)
    attn_mma<<<dim3(NHEADS, S_LEN / 128), 256, ATT_SMEM_BYTES>>>();

    // Output projection (fp32 out)
    mma_gemm<<<dim3(HID / 128, S_LEN / 128), 256, GEMM_SMEM_BYTES>>>(
        Ah, WoTh, out, S_LEN, HID, HID);
}

// round 16
// speedup vs baseline: 1.2102x; 1.0190x over previous
#include <cuda_runtime.h>
#include <cuda_fp16.h>
#include <cstdint>

#define S_LEN   2048
#define HID     2048
#define NHEADS  32
#define KVHEADS 8
#define HDIM    64
#define KVW     (KVHEADS * HDIM)   // 512
#define QKVW    (HID + 2 * KVW)    // 3072
#define QKW     (HID + KVW)        // 2560 (Q|K region width)

// ---------------- scratch (__device__ globals; no allocs allowed) ----------
__device__ __align__(16) __half g_HSh[S_LEN * HID];    // hs, half, plain
__device__ __align__(16) __half g_WTh[QKVW * HID];     // WqT|WkT|WvT [N,K] plain
__device__ __align__(16) __half g_WoTh[HID * HID];     // WoT [N,K] plain
__device__ __align__(16) float  g_QKf[S_LEN * QKW];    // Q|K fp32 (pre-rope)
__device__ __align__(16) __half g_QKh[S_LEN * QKW];    // Q|K half, plain
__device__ __align__(16) __half g_Vt[KVW * S_LEN];     // V^T [feature][token], plain
__device__ __align__(16) __half g_Ah[S_LEN * HID];     // attn out, plain

// ---------------- helpers ---------------------------------------------------
__device__ __forceinline__ uint32_t smem_u32(const void* p) {
    uint32_t a;
    asm("{ .reg .u64 t; cvta.to.shared.u64 t, %1; cvt.u32.u64 %0, t; }" : "=r"(a) : "l"(p));
    return a;
}
__device__ __forceinline__ uint32_t pack_h2(float lo, float hi) {
    uint32_t r;
    asm("cvt.rn.f16x2.f32 %0, %1, %2;" : "=r"(r) : "f"(hi), "f"(lo));
    return r;
}
__device__ __forceinline__ float fexp2(float x) {
    float y;
    asm("ex2.approx.f32 %0, %1;" : "=f"(y) : "f"(x));
    return y;
}
__device__ __forceinline__ void ldsm4(uint32_t* r, uint32_t a) {
    asm volatile("ldmatrix.sync.aligned.m8n8.x4.shared.b16 {%0,%1,%2,%3}, [%4];"
        : "=r"(r[0]), "=r"(r[1]), "=r"(r[2]), "=r"(r[3]) : "r"(a));
}
__device__ __forceinline__ void mma_f16(float* d, const uint32_t* a,
                                        uint32_t b0, uint32_t b1) {
    asm volatile("mma.sync.aligned.m16n8k16.row.col.f32.f16.f16.f32 "
        "{%0,%1,%2,%3}, {%4,%5,%6,%7}, {%8,%9}, {%0,%1,%2,%3};"
        : "+f"(d[0]), "+f"(d[1]), "+f"(d[2]), "+f"(d[3])
        : "r"(a[0]), "r"(a[1]), "r"(a[2]), "r"(a[3]), "r"(b0), "r"(b1));
}
#define CP_ASYNC16(dst, src) \
    asm volatile("cp.async.cg.shared.global [%0], [%1], 16;" :: "r"(dst), "l"(src) : "memory")
#define CP_COMMIT()  asm volatile("cp.async.commit_group;" ::: "memory")
#define CP_WAIT(n)   asm volatile("cp.async.wait_group %0;" :: "n"(n) : "memory")

#define NSTAGE 3
// SMEM rows: 64 halves = 128B = 8 chunks of 16B; swizzle chunk ^= (row & 7).

// ---------------------------------------------------------------------------
// QKV GEMM: 256 threads, CTA tile 128x96, warp 32x48 (4Mx2N), 2 CTAs/SM,
// grid (32,16) = 512 CTAs. LDSM fragments, 3-stage cp.async, 1 barrier/chunk.
// Output: cols < QKW -> g_QKf fp32; cols >= QKW -> g_Vt (per-column check).
// ---------------------------------------------------------------------------
#define QSTAGE_BYTES ((128 + 96) * 128)
#define QGEMM_SMEM_BYTES (NSTAGE * QSTAGE_BYTES)

__device__ __forceinline__ void qkv_issue_stage(uint32_t sb, int m0, int n0,
                                                int kc, int buf, int tid)
{
    const uint32_t St = sb + buf * QSTAGE_BYTES;
#pragma unroll
    for (int t = 0; t < 7; t++) {
        const int cid = tid + t * 256;       // 0..1791
        const int row = cid >> 3;            // 0..223
        const int j   = cid & 7;
        const uint32_t cc = (uint32_t)(j ^ (row & 7));
        const __half* src = (row < 128)
            ? g_HSh + (size_t)(m0 + row) * HID + kc * 64 + j * 8
            : g_WTh + (size_t)(n0 + row - 128) * HID + kc * 64 + j * 8;
        CP_ASYNC16(St + row * 128 + cc * 16, src);
    }
}

__global__ __launch_bounds__(256, 2) void mma_gemm_qkv()
{
    extern __shared__ uint32_t smu[];
    const uint32_t sb = smem_u32(smu);
    const int tid  = threadIdx.x;
    const int wid  = tid >> 5;
    const int lane = tid & 31;
    const int g = lane >> 2;
    const int q = lane & 3;
    const int jj = lane >> 3;
    const int rr = lane & 7;
    const int m0 = blockIdx.y * 128;
    const int n0 = blockIdx.x * 96;
    const int wm = (wid & 3) * 32;
    const int wn = (wid >> 2) * 48;

    const int arow = wm + rr + (jj & 1) * 8;
    const int asw  = arow & 7;
    const int brow = wn + rr + (jj >> 1) * 8;
    const int bsw  = brow & 7;
    const int ajh  = jj >> 1;
    const int bjl  = jj & 1;

    float acc[2][6][4];
#pragma unroll
    for (int i = 0; i < 2; i++)
#pragma unroll
        for (int j = 0; j < 6; j++)
#pragma unroll
            for (int k = 0; k < 4; k++) acc[i][j][k] = 0.f;

    const int nch = HID / 64;   // 32
    qkv_issue_stage(sb, m0, n0, 0, 0, tid);
    CP_COMMIT();
    qkv_issue_stage(sb, m0, n0, 1, 1, tid);
    CP_COMMIT();

    int buf = 0;
    for (int kc = 0; kc < nch; kc++) {
        if (kc + 1 < nch) { CP_WAIT(1); } else { CP_WAIT(0); }
        __syncthreads();

        if (kc + 2 < nch) {
            const int nb = (buf + 2 >= NSTAGE) ? buf + 2 - NSTAGE : buf + 2;
            qkv_issue_stage(sb, m0, n0, kc + 2, nb, tid);
            CP_COMMIT();
        }

        const uint32_t sbA = sb + buf * QSTAGE_BYTES;
        const uint32_t aAdr = sbA + arow * 128;
        const uint32_t bAdr = sbA + 128 * 128 + brow * 128;

#pragma unroll
        for (int ks = 0; ks < 4; ks++) {
            const uint32_t ca = (uint32_t)((ks * 2 + ajh) ^ asw) * 16;
            const uint32_t cb = (uint32_t)((ks * 2 + bjl) ^ bsw) * 16;
            uint32_t af[2][4];
            ldsm4(af[0], aAdr + ca);
            ldsm4(af[1], aAdr + 2048 + ca);
            uint32_t bf[6][2];
#pragma unroll
            for (int np = 0; np < 3; np++) {
                uint32_t t4[4];
                ldsm4(t4, bAdr + np * 2048 + cb);
                bf[2 * np][0] = t4[0];     bf[2 * np][1] = t4[1];
                bf[2 * np + 1][0] = t4[2]; bf[2 * np + 1][1] = t4[3];
            }
#pragma unroll
            for (int fm = 0; fm < 2; fm++)
#pragma unroll
                for (int fn = 0; fn < 6; fn++)
                    mma_f16(acc[fm][fn], af[fm], bf[fn][0], bf[fn][1]);
        }
        buf = (buf + 1 == NSTAGE) ? 0 : buf + 1;
    }

#pragma unroll
    for (int fm = 0; fm < 2; fm++) {
        const int r0 = m0 + wm + fm * 16 + g;
#pragma unroll
        for (int fn = 0; fn < 6; fn++) {
            const int c = n0 + wn + fn * 8 + 2 * q;
            if (c >= QKW) {   // V region: transposed halves
                const int vr = c - QKW;
                g_Vt[(size_t)vr * S_LEN + r0]           = __float2half_rn(acc[fm][fn][0]);
                g_Vt[(size_t)(vr + 1) * S_LEN + r0]     = __float2half_rn(acc[fm][fn][1]);
                g_Vt[(size_t)vr * S_LEN + r0 + 8]       = __float2half_rn(acc[fm][fn][2]);
                g_Vt[(size_t)(vr + 1) * S_LEN + r0 + 8] = __float2half_rn(acc[fm][fn][3]);
            } else {          // Q|K region: fp32 (rope consumes)
                *(float2*)(g_QKf + (size_t)r0 * QKW + c) =
                    make_float2(acc[fm][fn][0], acc[fm][fn][1]);
                *(float2*)(g_QKf + (size_t)(r0 + 8) * QKW + c) =
                    make_float2(acc[fm][fn][2], acc[fm][fn][3]);
            }
        }
    }
}

// ---------------------------------------------------------------------------
// Wo GEMM: 256 threads, CTA 128x128, warp 64x32, LDSM fragments.
// ---------------------------------------------------------------------------
#define STAGE_BYTES (2 * 128 * 128)
#define GEMM_SMEM_BYTES (NSTAGE * STAGE_BYTES)

__device__ __forceinline__ void gemm_issue_stage(const __half* A, const __half* Bt,
                                                 uint32_t sb, int m0, int n0, int Kh,
                                                 int kc, int buf, int lrow, int lsel)
{
    const uint32_t St = sb + buf * STAGE_BYTES;
    const __half* Ap = A  + (size_t)(m0 + lrow) * Kh + kc * 64 + lsel * 32;
    const __half* Bp = Bt + (size_t)(n0 + lrow) * Kh + kc * 64 + lsel * 32;
    const uint32_t da = St + lrow * 128;
    const uint32_t db = da + 128 * 128;
    const int sw = lrow & 7;
#pragma unroll
    for (int j = 0; j < 4; j++) {
        const uint32_t cc = (uint32_t)((lsel * 4 + j) ^ sw) * 16;
        CP_ASYNC16(da + cc, Ap + j * 8);
        CP_ASYNC16(db + cc, Bp + j * 8);
    }
}

__global__ __launch_bounds__(256) void mma_gemm(const __half* __restrict__ A,
                                                const __half* __restrict__ Bt,
                                                float* __restrict__ Cf,
                                                int M, int N, int Kh)
{
    extern __shared__ uint32_t smu[];
    const uint32_t sb = smem_u32(smu);
    const int tid  = threadIdx.x;
    const int wid  = tid >> 5;
    const int lane = tid & 31;
    const int g = lane >> 2;
    const int q = lane & 3;
    const int jj = lane >> 3;
    const int rr = lane & 7;
    const int m0 = blockIdx.y * 128;
    const int n0 = blockIdx.x * 128;
    const int wm = (wid & 1) * 64;
    const int wn = (wid >> 1) * 32;

    const int lrow = tid >> 1;
    const int lsel = tid & 1;

    const int arow = wm + rr + (jj & 1) * 8;
    const int asw  = arow & 7;
    const int brow = wn + rr + (jj >> 1) * 8;
    const int bsw  = brow & 7;
    const int ajh  = jj >> 1;
    const int bjl  = jj & 1;

    float acc[4][4][4];
#pragma unroll
    for (int i = 0; i < 4; i++)
#pragma unroll
        for (int j = 0; j < 4; j++)
#pragma unroll
            for (int k = 0; k < 4; k++) acc[i][j][k] = 0.f;

    const int nch = Kh / 64;
    gemm_issue_stage(A, Bt, sb, m0, n0, Kh, 0, 0, lrow, lsel);
    CP_COMMIT();
    if (nch > 1) {
        gemm_issue_stage(A, Bt, sb, m0, n0, Kh, 1, 1, lrow, lsel);
        CP_COMMIT();
    }

    int buf = 0;
    for (int kc = 0; kc < nch; kc++) {
        if (kc + 1 < nch) { CP_WAIT(1); } else { CP_WAIT(0); }
        __syncthreads();

        if (kc + 2 < nch) {
            const int nb = (buf + 2 >= NSTAGE) ? buf + 2 - NSTAGE : buf + 2;
            gemm_issue_stage(A, Bt, sb, m0, n0, Kh, kc + 2, nb, lrow, lsel);
            CP_COMMIT();
        }

        const uint32_t sbA = sb + buf * STAGE_BYTES;
        const uint32_t aAdr = sbA + arow * 128;
        const uint32_t bAdr = sbA + 128 * 128 + brow * 128;

#pragma unroll
        for (int ks = 0; ks < 4; ks++) {
            const uint32_t ca = (uint32_t)((ks * 2 + ajh) ^ asw) * 16;
            const uint32_t cb = (uint32_t)((ks * 2 + bjl) ^ bsw) * 16;
            uint32_t af[4][4];
#pragma unroll
            for (int fm = 0; fm < 4; fm++)
                ldsm4(af[fm], aAdr + fm * 2048 + ca);
            uint32_t bf[4][2];
#pragma unroll
            for (int np = 0; np < 2; np++) {
                uint32_t t4[4];
                ldsm4(t4, bAdr + np * 2048 + cb);
                bf[2 * np][0] = t4[0];     bf[2 * np][1] = t4[1];
                bf[2 * np + 1][0] = t4[2]; bf[2 * np + 1][1] = t4[3];
            }
#pragma unroll
            for (int fm = 0; fm < 4; fm++)
#pragma unroll
                for (int fn = 0; fn < 4; fn++)
                    mma_f16(acc[fm][fn], af[fm], bf[fn][0], bf[fn][1]);
        }
        buf = (buf + 1 == NSTAGE) ? 0 : buf + 1;
    }

#pragma unroll
    for (int fm = 0; fm < 4; fm++) {
        const int r0 = m0 + wm + fm * 16 + g;
#pragma unroll
        for (int fn = 0; fn < 4; fn++) {
            const int c = n0 + wn + fn * 8 + 2 * q;
            *(float2*)(Cf + (size_t)r0 * N + c) =
                make_float2(acc[fm][fn][0], acc[fm][fn][1]);
            *(float2*)(Cf + (size_t)(r0 + 8) * N + c) =
                make_float2(acc[fm][fn][2], acc[fm][fn][3]);
        }
    }
}

// ---------------------------------------------------------------------------
// Fused prep: weight transposes (half, plain) + hs -> half (plain).
// ---------------------------------------------------------------------------
__global__ void prep_all(const float* __restrict__ hs,
                         const float* __restrict__ Wq, const float* __restrict__ Wk,
                         const float* __restrict__ Wv, const float* __restrict__ Wo)
{
    __shared__ float t[32][33];
    const int z = blockIdx.z;
    const int x = threadIdx.x, y = threadIdx.y;
    const int bx = blockIdx.x * 32;
    const int by = blockIdx.y * 32;

    if (z == 4) {
        const float* src = hs + (size_t)by * HID + bx;
        __half* dst = g_HSh + (size_t)by * HID + bx;
#pragma unroll
        for (int i = 0; i < 32; i += 8)
            dst[(size_t)(y + i) * HID + x] = __float2half_rn(src[(size_t)(y + i) * HID + x]);
        return;
    }

    const float* src;
    __half* dst;
    int C;
    if (z == 0)      { src = Wq; dst = g_WTh;                              C = HID; }
    else if (z == 1) { src = Wo; dst = g_WoTh;                             C = HID; }
    else if (z == 2) { src = Wk; dst = g_WTh + (size_t)HID * HID;          C = KVW; }
    else             { src = Wv; dst = g_WTh + (size_t)(HID + KVW) * HID;  C = KVW; }
    if (bx >= C) return;

#pragma unroll
    for (int i = 0; i < 32; i += 8)
        t[y + i][x] = src[(size_t)(by + y + i) * C + bx + x];
    __syncthreads();
#pragma unroll
    for (int i = 0; i < 32; i += 8)
        dst[(size_t)(bx + y + i) * HID + by + x] = __float2half_rn(t[x][y + i]);
}

// ---------------------------------------------------------------------------
// RoPE: g_QKf (fp32) -> g_QKh (half, plain). Q scale = log2(e)/8.
// ---------------------------------------------------------------------------
__global__ __launch_bounds__(256) void rope_kernel()
{
    const int s = blockIdx.x;
    const int w = threadIdx.x >> 5;
    const int i = threadIdx.x & 31;
    const int h = blockIdx.y * 8 + w;      // 0..39

    const bool isQ = (h < NHEADS);
    const int base = isQ ? h * HDIM : HID + (h - NHEADS) * HDIM;
    const float scale = isQ ? 0.125f * 1.4426950408889634f : 1.0f;

    const float* src = g_QKf + (size_t)s * QKW + base;
    __half* dst = g_QKh + (size_t)s * QKW + base;

    float x1 = src[i];
    float x2 = src[i + 32];
    const float LN10000 = 9.210340371976184f;
    float inv = expf(-(float)i * (LN10000 / 32.0f));
    float ang = (float)s * inv;
    float c, sn;
    sincosf(ang, &sn, &c);
    dst[i]      = __float2half_rn((x1 * c - x2 * sn) * scale);
    dst[i + 32] = __float2half_rn((x2 * c + x1 * sn) * scale);
}

// ---------------------------------------------------------------------------
// fp16 tensor-core causal GQA flash attention (no-max softmax, base-2).
// One qb per CTA, 512 CTAs, heavy-first. LDSM fragments.
// 3-buffer K/V pipeline, ONE barrier per tile.
// ---------------------------------------------------------------------------
#define ATT_Q_BYTES  (128 * 128)
#define ATT_KV_BYTES (64 * 128)
#define ATT_SMEM_BYTES (ATT_Q_BYTES + 6 * ATT_KV_BYTES)   // 64 KB

__device__ __forceinline__ void attn_issue_kv(uint32_t kd, uint32_t vd,
                                              int k0, int kvh, int tid)
{
    const int lr = tid >> 2;
    const int jb = (tid & 3) * 2;
    const __half* kg = g_QKh + (size_t)(k0 + lr) * QKW + HID + kvh * HDIM;
    const __half* vg = g_Vt + (size_t)(kvh * HDIM + lr) * S_LEN + k0;
    const int sw = lr & 7;
    kd += lr * 128;
    vd += lr * 128;
#pragma unroll
    for (int e = 0; e < 2; e++) {
        const int j = jb + e;
        const uint32_t cc = (uint32_t)(j ^ sw) * 16;
        CP_ASYNC16(kd + cc, kg + j * 8);
        CP_ASYNC16(vd + cc, vg + j * 8);
    }
}

__global__ __launch_bounds__(256, 2) void attn_mma()
{
    extern __shared__ uint32_t smu[];
    const uint32_t sb  = smem_u32(smu);
    const uint32_t sbQ = sb;
    const uint32_t sbK = sb + ATT_Q_BYTES;                 // 3 x 8KB
    const uint32_t sbV = sbK + 3 * ATT_KV_BYTES;           // 3 x 8KB

    const int head = blockIdx.x;
    const int qb   = (gridDim.y - 1) - blockIdx.y;   // heavy CTAs first
    const int kvh  = head % KVHEADS;
    const int q0   = qb * 128;
    const int tid  = threadIdx.x;
    const int wid  = tid >> 5;
    const int lane = tid & 31;
    const int g = lane >> 2, q = lane & 3;
    const int jj = lane >> 3, rr = lane & 7;
    const int wm = wid * 16;

    const int arow = wm + rr + (jj & 1) * 8;   // Q lane row
    const int asw  = arow & 7;
    const int brow = rr + (jj >> 1) * 8;       // K/V lane row (base)
    const int bsw  = brow & 7;
    const int ajh  = jj >> 1;
    const int bjl  = jj & 1;

    const int T = 2 * qb + 2;
    attn_issue_kv(sbK, sbV, 0, kvh, tid);
    CP_COMMIT();
    attn_issue_kv(sbK + ATT_KV_BYTES, sbV + ATT_KV_BYTES, 64, kvh, tid);  // T>=2 always
    CP_COMMIT();

    // Q tile (128 x 64 halves) -> Qs, plain order, swizzled chunks
    {
        const int r  = tid >> 1;
        const int sw = r & 7;
        const __half* src = g_QKh + (size_t)(q0 + r) * QKW + head * HDIM + (tid & 1) * 32;
        const uint32_t dst = sbQ + r * 128;
#pragma unroll
        for (int j = 0; j < 4; j++) {
            const uint4 v = *(const uint4*)(src + j * 8);
            const uint32_t cc = (uint32_t)(((tid & 1) * 4 + j) ^ sw) * 16;
            asm volatile("st.shared.v4.b32 [%0], {%1,%2,%3,%4};"
                :: "r"(dst + cc), "r"(v.x), "r"(v.y), "r"(v.z), "r"(v.w) : "memory");
        }
    }
    __syncthreads();

    uint32_t qf[4][4];
#pragma unroll
    for (int ks = 0; ks < 4; ks++) {
        const uint32_t ca = (uint32_t)((ks * 2 + ajh) ^ asw) * 16;
        ldsm4(qf[ks], sbQ + arow * 128 + ca);
    }

    float o[8][4];
#pragma unroll
    for (int nf = 0; nf < 8; nf++)
#pragma unroll
        for (int j = 0; j < 4; j++) o[nf][j] = 0.f;
    float l0 = 0.f, l1 = 0.f;

    int buf = 0;
    for (int t = 0; t < T; t++) {
        if (t + 1 < T) { CP_WAIT(1); } else { CP_WAIT(0); }
        __syncthreads();

        // issue t+2 into buf (t+2)%3 == (t-1)%3: all readers past the barrier
        if (t + 2 < T) {
            const int nb = (buf + 2 >= 3) ? buf + 2 - 3 : buf + 2;
            attn_issue_kv(sbK + nb * ATT_KV_BYTES, sbV + nb * ATT_KV_BYTES,
                          (t + 2) * 64, kvh, tid);
            CP_COMMIT();
        }

        const int k0 = t * 64;
        const bool active = (k0 <= q0 + wm + 15);   // warp-uniform

        if (active) {
            const uint32_t kAdr = sbK + buf * ATT_KV_BYTES + brow * 128;
            const uint32_t vAdr = sbV + buf * ATT_KV_BYTES + brow * 128;

            // ---- S = Q K^T (base-2 log domain) ----
            float s[8][4];
#pragma unroll
            for (int nf = 0; nf < 8; nf++)
#pragma unroll
                for (int j = 0; j < 4; j++) s[nf][j] = 0.f;

#pragma unroll
            for (int ks = 0; ks < 4; ks++) {
                const uint32_t cb = (uint32_t)((ks * 2 + bjl) ^ bsw) * 16;
#pragma unroll
                for (int np = 0; np < 4; np++) {
                    uint32_t t4[4];
                    ldsm4(t4, kAdr + np * 2048 + cb);
                    mma_f16(s[2 * np],     qf[ks], t4[0], t4[1]);
                    mma_f16(s[2 * np + 1], qf[ks], t4[2], t4[3]);
                }
            }

            // ---- causal mask ----
            if (k0 + 63 > q0 + wm) {
                const int row0 = q0 + wm + g;
#pragma unroll
                for (int nf = 0; nf < 8; nf++) {
                    const int c = k0 + nf * 8 + 2 * q;
                    if (c     > row0)     s[nf][0] = -1e30f;
                    if (c + 1 > row0)     s[nf][1] = -1e30f;
                    if (c     > row0 + 8) s[nf][2] = -1e30f;
                    if (c + 1 > row0 + 8) s[nf][3] = -1e30f;
                }
            }

            // ---- softmax numerator: raw ex2 ----
            float rs0 = 0.f, rs1 = 0.f;
#pragma unroll
            for (int nf = 0; nf < 8; nf++) {
                s[nf][0] = fexp2(s[nf][0]);
                s[nf][1] = fexp2(s[nf][1]);
                s[nf][2] = fexp2(s[nf][2]);
                s[nf][3] = fexp2(s[nf][3]);
                rs0 += s[nf][0] + s[nf][1];
                rs1 += s[nf][2] + s[nf][3];
            }
            rs0 += __shfl_xor_sync(0xffffffffu, rs0, 1);
            rs0 += __shfl_xor_sync(0xffffffffu, rs0, 2);
            rs1 += __shfl_xor_sync(0xffffffffu, rs1, 1);
            rs1 += __shfl_xor_sync(0xffffffffu, rs1, 2);
            l0 += rs0;
            l1 += rs1;

            // ---- O += P V : P frags from accumulators; V via LDSM ----
#pragma unroll
            for (int kb = 0; kb < 4; kb++) {
                uint32_t pa[4];
                pa[0] = pack_h2(s[2 * kb][0],     s[2 * kb][1]);
                pa[1] = pack_h2(s[2 * kb][2],     s[2 * kb][3]);
                pa[2] = pack_h2(s[2 * kb + 1][0], s[2 * kb + 1][1]);
                pa[3] = pack_h2(s[2 * kb + 1][2], s[2 * kb + 1][3]);
                const uint32_t cv = (uint32_t)((kb * 2 + bjl) ^ bsw) * 16;
#pragma unroll
                for (int np = 0; np < 4; np++) {
                    uint32_t t4[4];
                    ldsm4(t4, vAdr + np * 2048 + cv);
                    mma_f16(o[2 * np],     pa, t4[0], t4[1]);
                    mma_f16(o[2 * np + 1], pa, t4[2], t4[3]);
                }
            }
        }
        buf = (buf + 1 == 3) ? 0 : buf + 1;
    }

    // ---- epilogue: normalize, write g_Ah plain ----
    const float inv0 = 1.f / l0;
    const float inv1 = 1.f / l1;
    const int row0 = q0 + wm + g;
    half2* Ah2 = (half2*)g_Ah;
#pragma unroll
    for (int nf = 0; nf < 8; nf++) {
        const int pos = head * 32 + 4 * nf + q;
        Ah2[(size_t)row0 * (HID / 2) + pos] =
            __floats2half2_rn(o[nf][0] * inv0, o[nf][1] * inv0);
        Ah2[(size_t)(row0 + 8) * (HID / 2) + pos] =
            __floats2half2_rn(o[nf][2] * inv1, o[nf][3] * inv1);
    }
}

// ---------------------------------------------------------------------------
extern "C" void kernel_launch(void* const* d_in, const int* in_sizes, int n_in,
                              void* d_out, int out_size)
{
    const float* hs = (const float*)d_in[0];
    const float* Wq = (const float*)d_in[1];
    const float* Wk = (const float*)d_in[2];
    const float* Wv = (const float*)d_in[3];
    const float* Wo = (const float*)d_in[4];
    float* out = (float*)d_out;

    __half *Ah, *WoTh;
    cudaGetSymbolAddress((void**)&Ah, g_Ah);
    cudaGetSymbolAddress((void**)&WoTh, g_WoTh);

    cudaFuncSetAttribute(mma_gemm_qkv, cudaFuncAttributeMaxDynamicSharedMemorySize,
                         QGEMM_SMEM_BYTES);
    cudaFuncSetAttribute(mma_gemm, cudaFuncAttributeMaxDynamicSharedMemorySize,
                         GEMM_SMEM_BYTES);
    cudaFuncSetAttribute(attn_mma, cudaFuncAttributeMaxDynamicSharedMemorySize,
                         ATT_SMEM_BYTES);

    // Prep: weights -> half transposed (plain); hs -> half (plain)
    prep_all<<<dim3(64, 64, 5), dim3(32, 8)>>>(hs, Wq, Wk, Wv, Wo);

    // Fused QKV projection: Q|K -> fp32, V -> Vt half (128x96 tiles, 2 CTA/SM)
    mma_gemm_qkv<<<dim3(QKVW / 96, S_LEN / 128), 256, QGEMM_SMEM_BYTES>>>();

    // RoPE: fp32 -> half (Q pre-scaled by log2e/8)
    rope_kernel<<<dim3(S_LEN, 5), 256>>>();

    // fp16 tensor-core causal attention (3-buffer pipeline, 1 barrier/tile)
    attn_mma<<<dim3(NHEADS, S_LEN / 128), 256, ATT_SMEM_BYTES>>>();

    // Output projection (fp32 out)
    mma_gemm<<<dim3(HID / 128, S_LEN / 128), 256, GEMM_SMEM_BYTES>>>(
        Ah, WoTh, out, S_LEN, HID, HID);
}

// round 17
// speedup vs baseline: 1.2424x; 1.0266x over previous
#include <cuda_runtime.h>
#include <cuda_fp16.h>
#include <cstdint>

#define S_LEN   2048
#define HID     2048
#define NHEADS  32
#define KVHEADS 8
#define HDIM    64
#define KVW     (KVHEADS * HDIM)   // 512
#define QKVW    (HID + 2 * KVW)    // 3072
#define QKW     (HID + KVW)        // 2560 (Q|K region width)

// ---------------- scratch (__device__ globals; no allocs allowed) ----------
__device__ __align__(16) __half g_HSh[S_LEN * HID];    // hs, half, plain
__device__ __align__(16) __half g_WTh[QKVW * HID];     // WqT|WkT|WvT [N,K] plain
__device__ __align__(16) __half g_WoTh[HID * HID];     // WoT [N,K] plain
__device__ __align__(16) float  g_QKf[S_LEN * QKW];    // Q|K fp32 (pre-rope)
__device__ __align__(16) __half g_QKh[S_LEN * QKW];    // Q|K half, plain
__device__ __align__(16) __half g_Vt[KVW * S_LEN];     // V^T [feature][token], plain
__device__ __align__(16) __half g_Ah[S_LEN * HID];     // attn out, plain

// ---------------- helpers ---------------------------------------------------
__device__ __forceinline__ uint32_t smem_u32(const void* p) {
    uint32_t a;
    asm("{ .reg .u64 t; cvta.to.shared.u64 t, %1; cvt.u32.u64 %0, t; }" : "=r"(a) : "l"(p));
    return a;
}
__device__ __forceinline__ uint32_t pack_h2(float lo, float hi) {
    uint32_t r;
    asm("cvt.rn.f16x2.f32 %0, %1, %2;" : "=r"(r) : "f"(hi), "f"(lo));
    return r;
}
__device__ __forceinline__ uint32_t h2exp2(uint32_t x) {
    uint32_t y;
    asm("ex2.approx.f16x2 %0, %1;" : "=r"(y) : "r"(x));
    return y;
}
__device__ __forceinline__ uint32_t hadd2u(uint32_t a, uint32_t b) {
    uint32_t d;
    asm("add.f16x2 %0, %1, %2;" : "=r"(d) : "r"(a), "r"(b));
    return d;
}
__device__ __forceinline__ float h2sum(uint32_t h) {
    const __half2 v = *(const __half2*)&h;
    return __half2float(__low2half(v)) + __half2float(__high2half(v));
}
__device__ __forceinline__ void ldsm4(uint32_t* r, uint32_t a) {
    asm volatile("ldmatrix.sync.aligned.m8n8.x4.shared.b16 {%0,%1,%2,%3}, [%4];"
        : "=r"(r[0]), "=r"(r[1]), "=r"(r[2]), "=r"(r[3]) : "r"(a));
}
__device__ __forceinline__ void mma_f16(float* d, const uint32_t* a,
                                        uint32_t b0, uint32_t b1) {
    asm volatile("mma.sync.aligned.m16n8k16.row.col.f32.f16.f16.f32 "
        "{%0,%1,%2,%3}, {%4,%5,%6,%7}, {%8,%9}, {%0,%1,%2,%3};"
        : "+f"(d[0]), "+f"(d[1]), "+f"(d[2]), "+f"(d[3])
        : "r"(a[0]), "r"(a[1]), "r"(a[2]), "r"(a[3]), "r"(b0), "r"(b1));
}
#define CP_ASYNC16(dst, src) \
    asm volatile("cp.async.cg.shared.global [%0], [%1], 16;" :: "r"(dst), "l"(src) : "memory")
#define CP_COMMIT()  asm volatile("cp.async.commit_group;" ::: "memory")
#define CP_WAIT(n)   asm volatile("cp.async.wait_group %0;" :: "n"(n) : "memory")

#define NSTAGE 3
// SMEM rows: 64 halves = 128B = 8 chunks of 16B; swizzle chunk ^= (row & 7).

// ---------------------------------------------------------------------------
// QKV GEMM: 256 threads, CTA tile 128x96, warp 32x48 (4Mx2N), 2 CTAs/SM.
// ---------------------------------------------------------------------------
#define QSTAGE_BYTES ((128 + 96) * 128)
#define QGEMM_SMEM_BYTES (NSTAGE * QSTAGE_BYTES)

__device__ __forceinline__ void qkv_issue_stage(uint32_t sb, int m0, int n0,
                                                int kc, int buf, int tid)
{
    const uint32_t St = sb + buf * QSTAGE_BYTES;
#pragma unroll
    for (int t = 0; t < 7; t++) {
        const int cid = tid + t * 256;       // 0..1791
        const int row = cid >> 3;            // 0..223
        const int j   = cid & 7;
        const uint32_t cc = (uint32_t)(j ^ (row & 7));
        const __half* src = (row < 128)
            ? g_HSh + (size_t)(m0 + row) * HID + kc * 64 + j * 8
            : g_WTh + (size_t)(n0 + row - 128) * HID + kc * 64 + j * 8;
        CP_ASYNC16(St + row * 128 + cc * 16, src);
    }
}

__global__ __launch_bounds__(256, 2) void mma_gemm_qkv()
{
    extern __shared__ uint32_t smu[];
    const uint32_t sb = smem_u32(smu);
    const int tid  = threadIdx.x;
    const int wid  = tid >> 5;
    const int lane = tid & 31;
    const int g = lane >> 2;
    const int q = lane & 3;
    const int jj = lane >> 3;
    const int rr = lane & 7;
    const int m0 = blockIdx.y * 128;
    const int n0 = blockIdx.x * 96;
    const int wm = (wid & 3) * 32;
    const int wn = (wid >> 2) * 48;

    const int arow = wm + rr + (jj & 1) * 8;
    const int asw  = arow & 7;
    const int brow = wn + rr + (jj >> 1) * 8;
    const int bsw  = brow & 7;
    const int ajh  = jj >> 1;
    const int bjl  = jj & 1;

    float acc[2][6][4];
#pragma unroll
    for (int i = 0; i < 2; i++)
#pragma unroll
        for (int j = 0; j < 6; j++)
#pragma unroll
            for (int k = 0; k < 4; k++) acc[i][j][k] = 0.f;

    const int nch = HID / 64;   // 32
    qkv_issue_stage(sb, m0, n0, 0, 0, tid);
    CP_COMMIT();
    qkv_issue_stage(sb, m0, n0, 1, 1, tid);
    CP_COMMIT();

    int buf = 0;
    for (int kc = 0; kc < nch; kc++) {
        if (kc + 1 < nch) { CP_WAIT(1); } else { CP_WAIT(0); }
        __syncthreads();

        if (kc + 2 < nch) {
            const int nb = (buf + 2 >= NSTAGE) ? buf + 2 - NSTAGE : buf + 2;
            qkv_issue_stage(sb, m0, n0, kc + 2, nb, tid);
            CP_COMMIT();
        }

        const uint32_t sbA = sb + buf * QSTAGE_BYTES;
        const uint32_t aAdr = sbA + arow * 128;
        const uint32_t bAdr = sbA + 128 * 128 + brow * 128;

#pragma unroll
        for (int ks = 0; ks < 4; ks++) {
            const uint32_t ca = (uint32_t)((ks * 2 + ajh) ^ asw) * 16;
            const uint32_t cb = (uint32_t)((ks * 2 + bjl) ^ bsw) * 16;
            uint32_t af[2][4];
            ldsm4(af[0], aAdr + ca);
            ldsm4(af[1], aAdr + 2048 + ca);
            uint32_t bf[6][2];
#pragma unroll
            for (int np = 0; np < 3; np++) {
                uint32_t t4[4];
                ldsm4(t4, bAdr + np * 2048 + cb);
                bf[2 * np][0] = t4[0];     bf[2 * np][1] = t4[1];
                bf[2 * np + 1][0] = t4[2]; bf[2 * np + 1][1] = t4[3];
            }
#pragma unroll
            for (int fm = 0; fm < 2; fm++)
#pragma unroll
                for (int fn = 0; fn < 6; fn++)
                    mma_f16(acc[fm][fn], af[fm], bf[fn][0], bf[fn][1]);
        }
        buf = (buf + 1 == NSTAGE) ? 0 : buf + 1;
    }

#pragma unroll
    for (int fm = 0; fm < 2; fm++) {
        const int r0 = m0 + wm + fm * 16 + g;
#pragma unroll
        for (int fn = 0; fn < 6; fn++) {
            const int c = n0 + wn + fn * 8 + 2 * q;
            if (c >= QKW) {   // V region: transposed halves
                const int vr = c - QKW;
                g_Vt[(size_t)vr * S_LEN + r0]           = __float2half_rn(acc[fm][fn][0]);
                g_Vt[(size_t)(vr + 1) * S_LEN + r0]     = __float2half_rn(acc[fm][fn][1]);
                g_Vt[(size_t)vr * S_LEN + r0 + 8]       = __float2half_rn(acc[fm][fn][2]);
                g_Vt[(size_t)(vr + 1) * S_LEN + r0 + 8] = __float2half_rn(acc[fm][fn][3]);
            } else {          // Q|K region: fp32 (rope consumes)
                *(float2*)(g_QKf + (size_t)r0 * QKW + c) =
                    make_float2(acc[fm][fn][0], acc[fm][fn][1]);
                *(float2*)(g_QKf + (size_t)(r0 + 8) * QKW + c) =
                    make_float2(acc[fm][fn][2], acc[fm][fn][3]);
            }
        }
    }
}

// ---------------------------------------------------------------------------
// Wo GEMM: 256 threads, CTA 128x128, warp 64x32, LDSM; force 2 CTAs/SM.
// ---------------------------------------------------------------------------
#define STAGE_BYTES (2 * 128 * 128)
#define GEMM_SMEM_BYTES (NSTAGE * STAGE_BYTES)

__device__ __forceinline__ void gemm_issue_stage(const __half* A, const __half* Bt,
                                                 uint32_t sb, int m0, int n0, int Kh,
                                                 int kc, int buf, int lrow, int lsel)
{
    const uint32_t St = sb + buf * STAGE_BYTES;
    const __half* Ap = A  + (size_t)(m0 + lrow) * Kh + kc * 64 + lsel * 32;
    const __half* Bp = Bt + (size_t)(n0 + lrow) * Kh + kc * 64 + lsel * 32;
    const uint32_t da = St + lrow * 128;
    const uint32_t db = da + 128 * 128;
    const int sw = lrow & 7;
#pragma unroll
    for (int j = 0; j < 4; j++) {
        const uint32_t cc = (uint32_t)((lsel * 4 + j) ^ sw) * 16;
        CP_ASYNC16(da + cc, Ap + j * 8);
        CP_ASYNC16(db + cc, Bp + j * 8);
    }
}

__global__ __launch_bounds__(256, 2) void mma_gemm(const __half* __restrict__ A,
                                                   const __half* __restrict__ Bt,
                                                   float* __restrict__ Cf,
                                                   int M, int N, int Kh)
{
    extern __shared__ uint32_t smu[];
    const uint32_t sb = smem_u32(smu);
    const int tid  = threadIdx.x;
    const int wid  = tid >> 5;
    const int lane = tid & 31;
    const int g = lane >> 2;
    const int q = lane & 3;
    const int jj = lane >> 3;
    const int rr = lane & 7;
    const int m0 = blockIdx.y * 128;
    const int n0 = blockIdx.x * 128;
    const int wm = (wid & 1) * 64;
    const int wn = (wid >> 1) * 32;

    const int lrow = tid >> 1;
    const int lsel = tid & 1;

    const int arow = wm + rr + (jj & 1) * 8;
    const int asw  = arow & 7;
    const int brow = wn + rr + (jj >> 1) * 8;
    const int bsw  = brow & 7;
    const int ajh  = jj >> 1;
    const int bjl  = jj & 1;

    float acc[4][4][4];
#pragma unroll
    for (int i = 0; i < 4; i++)
#pragma unroll
        for (int j = 0; j < 4; j++)
#pragma unroll
            for (int k = 0; k < 4; k++) acc[i][j][k] = 0.f;

    const int nch = Kh / 64;
    gemm_issue_stage(A, Bt, sb, m0, n0, Kh, 0, 0, lrow, lsel);
    CP_COMMIT();
    if (nch > 1) {
        gemm_issue_stage(A, Bt, sb, m0, n0, Kh, 1, 1, lrow, lsel);
        CP_COMMIT();
    }

    int buf = 0;
    for (int kc = 0; kc < nch; kc++) {
        if (kc + 1 < nch) { CP_WAIT(1); } else { CP_WAIT(0); }
        __syncthreads();

        if (kc + 2 < nch) {
            const int nb = (buf + 2 >= NSTAGE) ? buf + 2 - NSTAGE : buf + 2;
            gemm_issue_stage(A, Bt, sb, m0, n0, Kh, kc + 2, nb, lrow, lsel);
            CP_COMMIT();
        }

        const uint32_t sbA = sb + buf * STAGE_BYTES;
        const uint32_t aAdr = sbA + arow * 128;
        const uint32_t bAdr = sbA + 128 * 128 + brow * 128;

#pragma unroll
        for (int ks = 0; ks < 4; ks++) {
            const uint32_t ca = (uint32_t)((ks * 2 + ajh) ^ asw) * 16;
            const uint32_t cb = (uint32_t)((ks * 2 + bjl) ^ bsw) * 16;
            uint32_t af[4][4];
#pragma unroll
            for (int fm = 0; fm < 4; fm++)
                ldsm4(af[fm], aAdr + fm * 2048 + ca);
            uint32_t bf[4][2];
#pragma unroll
            for (int np = 0; np < 2; np++) {
                uint32_t t4[4];
                ldsm4(t4, bAdr + np * 2048 + cb);
                bf[2 * np][0] = t4[0];     bf[2 * np][1] = t4[1];
                bf[2 * np + 1][0] = t4[2]; bf[2 * np + 1][1] = t4[3];
            }
#pragma unroll
            for (int fm = 0; fm < 4; fm++)
#pragma unroll
                for (int fn = 0; fn < 4; fn++)
                    mma_f16(acc[fm][fn], af[fm], bf[fn][0], bf[fn][1]);
        }
        buf = (buf + 1 == NSTAGE) ? 0 : buf + 1;
    }

#pragma unroll
    for (int fm = 0; fm < 4; fm++) {
        const int r0 = m0 + wm + fm * 16 + g;
#pragma unroll
        for (int fn = 0; fn < 4; fn++) {
            const int c = n0 + wn + fn * 8 + 2 * q;
            *(float2*)(Cf + (size_t)r0 * N + c) =
                make_float2(acc[fm][fn][0], acc[fm][fn][1]);
            *(float2*)(Cf + (size_t)(r0 + 8) * N + c) =
                make_float2(acc[fm][fn][2], acc[fm][fn][3]);
        }
    }
}

// ---------------------------------------------------------------------------
// Fused prep: weight transposes (half, plain) + hs -> half (plain).
// ---------------------------------------------------------------------------
__global__ void prep_all(const float* __restrict__ hs,
                         const float* __restrict__ Wq, const float* __restrict__ Wk,
                         const float* __restrict__ Wv, const float* __restrict__ Wo)
{
    __shared__ float t[32][33];
    const int z = blockIdx.z;
    const int x = threadIdx.x, y = threadIdx.y;
    const int bx = blockIdx.x * 32;
    const int by = blockIdx.y * 32;

    if (z == 4) {
        const float* src = hs + (size_t)by * HID + bx;
        __half* dst = g_HSh + (size_t)by * HID + bx;
#pragma unroll
        for (int i = 0; i < 32; i += 8)
            dst[(size_t)(y + i) * HID + x] = __float2half_rn(src[(size_t)(y + i) * HID + x]);
        return;
    }

    const float* src;
    __half* dst;
    int C;
    if (z == 0)      { src = Wq; dst = g_WTh;                              C = HID; }
    else if (z == 1) { src = Wo; dst = g_WoTh;                             C = HID; }
    else if (z == 2) { src = Wk; dst = g_WTh + (size_t)HID * HID;          C = KVW; }
    else             { src = Wv; dst = g_WTh + (size_t)(HID + KVW) * HID;  C = KVW; }
    if (bx >= C) return;

#pragma unroll
    for (int i = 0; i < 32; i += 8)
        t[y + i][x] = src[(size_t)(by + y + i) * C + bx + x];
    __syncthreads();
#pragma unroll
    for (int i = 0; i < 32; i += 8)
        dst[(size_t)(bx + y + i) * HID + by + x] = __float2half_rn(t[x][y + i]);
}

// ---------------------------------------------------------------------------
// RoPE: g_QKf (fp32) -> g_QKh (half, plain). Q scale = log2(e)/8.
// ---------------------------------------------------------------------------
__global__ __launch_bounds__(256) void rope_kernel()
{
    const int s = blockIdx.x;
    const int w = threadIdx.x >> 5;
    const int i = threadIdx.x & 31;
    const int h = blockIdx.y * 8 + w;      // 0..39

    const bool isQ = (h < NHEADS);
    const int base = isQ ? h * HDIM : HID + (h - NHEADS) * HDIM;
    const float scale = isQ ? 0.125f * 1.4426950408889634f : 1.0f;

    const float* src = g_QKf + (size_t)s * QKW + base;
    __half* dst = g_QKh + (size_t)s * QKW + base;

    float x1 = src[i];
    float x2 = src[i + 32];
    const float LN10000 = 9.210340371976184f;
    float inv = expf(-(float)i * (LN10000 / 32.0f));
    float ang = (float)s * inv;
    float c, sn;
    sincosf(ang, &sn, &c);
    dst[i]      = __float2half_rn((x1 * c - x2 * sn) * scale);
    dst[i + 32] = __float2half_rn((x2 * c + x1 * sn) * scale);
}

// ---------------------------------------------------------------------------
// fp16 tensor-core causal GQA flash attention (no-max softmax, base-2).
// f16x2 exp: pack raw scores -> ex2.approx.f16x2 (halves MUFU pressure);
// row sums via HADD2 tree. P frags feed PV directly.
// ---------------------------------------------------------------------------
#define ATT_Q_BYTES  (128 * 128)
#define ATT_KV_BYTES (64 * 128)
#define ATT_SMEM_BYTES (ATT_Q_BYTES + 6 * ATT_KV_BYTES)   // 64 KB

__device__ __forceinline__ void attn_issue_kv(uint32_t kd, uint32_t vd,
                                              int k0, int kvh, int tid)
{
    const int lr = tid >> 2;
    const int jb = (tid & 3) * 2;
    const __half* kg = g_QKh + (size_t)(k0 + lr) * QKW + HID + kvh * HDIM;
    const __half* vg = g_Vt + (size_t)(kvh * HDIM + lr) * S_LEN + k0;
    const int sw = lr & 7;
    kd += lr * 128;
    vd += lr * 128;
#pragma unroll
    for (int e = 0; e < 2; e++) {
        const int j = jb + e;
        const uint32_t cc = (uint32_t)(j ^ sw) * 16;
        CP_ASYNC16(kd + cc, kg + j * 8);
        CP_ASYNC16(vd + cc, vg + j * 8);
    }
}

__global__ __launch_bounds__(256, 2) void attn_mma()
{
    extern __shared__ uint32_t smu[];
    const uint32_t sb  = smem_u32(smu);
    const uint32_t sbQ = sb;
    const uint32_t sbK = sb + ATT_Q_BYTES;                 // 3 x 8KB
    const uint32_t sbV = sbK + 3 * ATT_KV_BYTES;           // 3 x 8KB

    const int head = blockIdx.x;
    const int qb   = (gridDim.y - 1) - blockIdx.y;   // heavy CTAs first
    const int kvh  = head % KVHEADS;
    const int q0   = qb * 128;
    const int tid  = threadIdx.x;
    const int wid  = tid >> 5;
    const int lane = tid & 31;
    const int g = lane >> 2, q = lane & 3;
    const int jj = lane >> 3, rr = lane & 7;
    const int wm = wid * 16;

    const int arow = wm + rr + (jj & 1) * 8;   // Q lane row
    const int asw  = arow & 7;
    const int brow = rr + (jj >> 1) * 8;       // K/V lane row (base)
    const int bsw  = brow & 7;
    const int ajh  = jj >> 1;
    const int bjl  = jj & 1;

    const int T = 2 * qb + 2;
    attn_issue_kv(sbK, sbV, 0, kvh, tid);
    CP_COMMIT();
    attn_issue_kv(sbK + ATT_KV_BYTES, sbV + ATT_KV_BYTES, 64, kvh, tid);
    CP_COMMIT();

    // Q tile (128 x 64 halves) -> Qs, plain order, swizzled chunks
    {
        const int r  = tid >> 1;
        const int sw = r & 7;
        const __half* src = g_QKh + (size_t)(q0 + r) * QKW + head * HDIM + (tid & 1) * 32;
        const uint32_t dst = sbQ + r * 128;
#pragma unroll
        for (int j = 0; j < 4; j++) {
            const uint4 v = *(const uint4*)(src + j * 8);
            const uint32_t cc = (uint32_t)(((tid & 1) * 4 + j) ^ sw) * 16;
            asm volatile("st.shared.v4.b32 [%0], {%1,%2,%3,%4};"
                :: "r"(dst + cc), "r"(v.x), "r"(v.y), "r"(v.z), "r"(v.w) : "memory");
        }
    }
    __syncthreads();

    uint32_t qf[4][4];
#pragma unroll
    for (int ks = 0; ks < 4; ks++) {
        const uint32_t ca = (uint32_t)((ks * 2 + ajh) ^ asw) * 16;
        ldsm4(qf[ks], sbQ + arow * 128 + ca);
    }

    float o[8][4];
#pragma unroll
    for (int nf = 0; nf < 8; nf++)
#pragma unroll
        for (int j = 0; j < 4; j++) o[nf][j] = 0.f;
    float l0 = 0.f, l1 = 0.f;

    int buf = 0;
    for (int t = 0; t < T; t++) {
        if (t + 1 < T) { CP_WAIT(1); } else { CP_WAIT(0); }
        __syncthreads();

        if (t + 2 < T) {
            const int nb = (buf + 2 >= 3) ? buf + 2 - 3 : buf + 2;
            attn_issue_kv(sbK + nb * ATT_KV_BYTES, sbV + nb * ATT_KV_BYTES,
                          (t + 2) * 64, kvh, tid);
            CP_COMMIT();
        }

        const int k0 = t * 64;
        const bool active = (k0 <= q0 + wm + 15);   // warp-uniform

        if (active) {
            const uint32_t kAdr = sbK + buf * ATT_KV_BYTES + brow * 128;
            const uint32_t vAdr = sbV + buf * ATT_KV_BYTES + brow * 128;

            // ---- S = Q K^T (base-2 log domain) ----
            float s[8][4];
#pragma unroll
            for (int nf = 0; nf < 8; nf++)
#pragma unroll
                for (int j = 0; j < 4; j++) s[nf][j] = 0.f;

#pragma unroll
            for (int ks = 0; ks < 4; ks++) {
                const uint32_t cb = (uint32_t)((ks * 2 + bjl) ^ bsw) * 16;
#pragma unroll
                for (int np = 0; np < 4; np++) {
                    uint32_t t4[4];
                    ldsm4(t4, kAdr + np * 2048 + cb);
                    mma_f16(s[2 * np],     qf[ks], t4[0], t4[1]);
                    mma_f16(s[2 * np + 1], qf[ks], t4[2], t4[3]);
                }
            }

            // ---- causal mask ----
            if (k0 + 63 > q0 + wm) {
                const int row0 = q0 + wm + g;
#pragma unroll
                for (int nf = 0; nf < 8; nf++) {
                    const int c = k0 + nf * 8 + 2 * q;
                    if (c     > row0)     s[nf][0] = -1e30f;
                    if (c + 1 > row0)     s[nf][1] = -1e30f;
                    if (c     > row0 + 8) s[nf][2] = -1e30f;
                    if (c + 1 > row0 + 8) s[nf][3] = -1e30f;
                }
            }

            // ---- P = 2^S in f16x2 (half MUFU count; masked -> -inf -> 0) ----
            uint32_t pa[4][4];
#pragma unroll
            for (int kb = 0; kb < 4; kb++) {
                pa[kb][0] = h2exp2(pack_h2(s[2 * kb][0],     s[2 * kb][1]));
                pa[kb][1] = h2exp2(pack_h2(s[2 * kb][2],     s[2 * kb][3]));
                pa[kb][2] = h2exp2(pack_h2(s[2 * kb + 1][0], s[2 * kb + 1][1]));
                pa[kb][3] = h2exp2(pack_h2(s[2 * kb + 1][2], s[2 * kb + 1][3]));
            }

            // ---- row sums via HADD2 tree (<=512 per half, safe) ----
            uint32_t h0 = hadd2u(hadd2u(hadd2u(pa[0][0], pa[0][2]),
                                        hadd2u(pa[1][0], pa[1][2])),
                                 hadd2u(hadd2u(pa[2][0], pa[2][2]),
                                        hadd2u(pa[3][0], pa[3][2])));
            uint32_t h1 = hadd2u(hadd2u(hadd2u(pa[0][1], pa[0][3]),
                                        hadd2u(pa[1][1], pa[1][3])),
                                 hadd2u(hadd2u(pa[2][1], pa[2][3]),
                                        hadd2u(pa[3][1], pa[3][3])));
            float rs0 = h2sum(h0);
            float rs1 = h2sum(h1);
            rs0 += __shfl_xor_sync(0xffffffffu, rs0, 1);
            rs0 += __shfl_xor_sync(0xffffffffu, rs0, 2);
            rs1 += __shfl_xor_sync(0xffffffffu, rs1, 1);
            rs1 += __shfl_xor_sync(0xffffffffu, rs1, 2);
            l0 += rs0;
            l1 += rs1;

            // ---- O += P V : P frags direct; V via LDSM ----
#pragma unroll
            for (int kb = 0; kb < 4; kb++) {
                const uint32_t cv = (uint32_t)((kb * 2 + bjl) ^ bsw) * 16;
#pragma unroll
                for (int np = 0; np < 4; np++) {
                    uint32_t t4[4];
                    ldsm4(t4, vAdr + np * 2048 + cv);
                    mma_f16(o[2 * np],     pa[kb], t4[0], t4[1]);
                    mma_f16(o[2 * np + 1], pa[kb], t4[2], t4[3]);
                }
            }
        }
        buf = (buf + 1 == 3) ? 0 : buf + 1;
    }

    // ---- epilogue: normalize, write g_Ah plain ----
    const float inv0 = 1.f / l0;
    const float inv1 = 1.f / l1;
    const int row0 = q0 + wm + g;
    half2* Ah2 = (half2*)g_Ah;
#pragma unroll
    for (int nf = 0; nf < 8; nf++) {
        const int pos = head * 32 + 4 * nf + q;
        Ah2[(size_t)row0 * (HID / 2) + pos] =
            __floats2half2_rn(o[nf][0] * inv0, o[nf][1] * inv0);
        Ah2[(size_t)(row0 + 8) * (HID / 2) + pos] =
            __floats2half2_rn(o[nf][2] * inv1, o[nf][3] * inv1);
    }
}

// ---------------------------------------------------------------------------
extern "C" void kernel_launch(void* const* d_in, const int* in_sizes, int n_in,
                              void* d_out, int out_size)
{
    const float* hs = (const float*)d_in[0];
    const float* Wq = (const float*)d_in[1];
    const float* Wk = (const float*)d_in[2];
    const float* Wv = (const float*)d_in[3];
    const float* Wo = (const float*)d_in[4];
    float* out = (float*)d_out;

    __half *Ah, *WoTh;
    cudaGetSymbolAddress((void**)&Ah, g_Ah);
    cudaGetSymbolAddress((void**)&WoTh, g_WoTh);

    cudaFuncSetAttribute(mma_gemm_qkv, cudaFuncAttributeMaxDynamicSharedMemorySize,
                         QGEMM_SMEM_BYTES);
    cudaFuncSetAttribute(mma_gemm, cudaFuncAttributeMaxDynamicSharedMemorySize,
                         GEMM_SMEM_BYTES);
    cudaFuncSetAttribute(attn_mma, cudaFuncAttributeMaxDynamicSharedMemorySize,
                         ATT_SMEM_BYTES);

    // Prep: weights -> half transposed (plain); hs -> half (plain)
    prep_all<<<dim3(64, 64, 5), dim3(32, 8)>>>(hs, Wq, Wk, Wv, Wo);

    // Fused QKV projection: Q|K -> fp32, V -> Vt half
    mma_gemm_qkv<<<dim3(QKVW / 96, S_LEN / 128), 256, QGEMM_SMEM_BYTES>>>();

    // RoPE: fp32 -> half (Q pre-scaled by log2e/8)
    rope_kernel<<<dim3(S_LEN, 5), 256>>>();

    // fp16 tensor-core causal attention (f16x2 softmax)
    attn_mma<<<dim3(NHEADS, S_LEN / 128), 256, ATT_SMEM_BYTES>>>();

    // Output projection (fp32 out)
    mma_gemm<<<dim3(HID / 128, S_LEN / 128), 256, GEMM_SMEM_BYTES>>>(
        Ah, WoTh, out, S_LEN, HID, HID);
}